// round 10
// baseline (speedup 1.0000x reference)
#include <cuda_runtime.h>
#include <cstdint>
#include <cstddef>

#define NN   8192
#define FIN  256
#define FOUT 128
#define ALPHA_SLOPE 0.2f

#define PB_STRIDE 72
#define P_FLOATS  (64 * PB_STRIDE)     // 4608 per stage
#define NSTAGES   4
#define NTILES    (NN / 64)            // 128

// ---------------- scratch (device globals: no allocation allowed) ------------
// g_WhB: Wh pre-staged in MMA-B fragment layout per 64-row j-tile:
//   addr = tile*8192 + kt*1024 + f*8 + (kl&3)*2 + (kl>>2),  row = tile*64+kt*8+kl
__device__ float g_WhB[(size_t)NN * FOUT];
__device__ float g_f1[NN];
__device__ float g_f2[NN];
// bitmask of adj>0: word index = row*128 + s*8 + c8  (s = jt>>3), byte jt&7,
// bit b = column j = jt*64 + c8*8 + b.  (4 words for c8=h*4..h*4+3 contiguous)
__device__ unsigned long long g_mask[(size_t)NN * 128];

// ---------------- helpers ----------------------------------------------------
__device__ __forceinline__ float to_tf32(float x) {
    uint32_t u;
    asm("cvt.rna.tf32.f32 %0, %1;" : "=r"(u) : "f"(x));
    return __uint_as_float(u);
}

__device__ __forceinline__ void mma_tf32(float* c,
                                         uint32_t a0, uint32_t a1, uint32_t a2, uint32_t a3,
                                         uint32_t b0, uint32_t b1) {
    asm volatile(
        "mma.sync.aligned.m16n8k8.row.col.f32.tf32.tf32.f32 "
        "{%0,%1,%2,%3}, {%4,%5,%6,%7}, {%8,%9}, {%0,%1,%2,%3};\n"
        : "+f"(c[0]), "+f"(c[1]), "+f"(c[2]), "+f"(c[3])
        : "r"(a0), "r"(a1), "r"(a2), "r"(a3), "r"(b0), "r"(b1));
}

__device__ __forceinline__ float lrelu_exp(float s) {
    s = fmaxf(s, ALPHA_SLOPE * s);
    return __expf(s);
}

#define MBAR_INIT(addr, count) \
    asm volatile("mbarrier.init.shared.b64 [%0], %1;" :: "r"(addr), "r"(count) : "memory")
#define MBAR_ARRIVE(addr) \
    asm volatile("mbarrier.arrive.shared.b64 _, [%0];" :: "r"(addr) : "memory")
#define MBAR_WAIT(addr, ph) do {                                               \
    uint32_t _mb = (addr); uint32_t _p = (ph); uint32_t _done;                 \
    asm volatile(                                                              \
        "{\n\t.reg .pred p;\n\t"                                               \
        "mbarrier.try_wait.parity.acquire.cta.shared::cta.b64 p, [%1], %2;\n\t"\
        "selp.b32 %0, 1, 0, p;\n\t}"                                           \
        : "=r"(_done) : "r"(_mb), "r"(_p) : "memory");                         \
    if (!_done) {                                                              \
        asm volatile(                                                          \
            "{\n\t.reg .pred P1;\n\t"                                          \
            "WAIT_LOOP_%=:\n\t"                                                \
            "mbarrier.try_wait.parity.acquire.cta.shared::cta.b64 P1, [%0], %1, 0x989680;\n\t" \
            "@P1 bra.uni WAIT_DONE_%=;\n\t"                                    \
            "bra.uni WAIT_LOOP_%=;\n\t"                                        \
            "WAIT_DONE_%=:\n\t}"                                               \
            :: "r"(_mb), "r"(_p) : "memory");                                  \
    }                                                                          \
} while (0)

// ---------------- Kernel M: adj -> bitmask -----------------------------------
__global__ void __launch_bounds__(128) mask_kernel(const int* __restrict__ adj) {
    const int i  = blockIdx.x;
    const int t  = threadIdx.x;
    const int c8 = t & 7;
    const int s  = t >> 3;

    const int* row = adj + (size_t)i * NN;
    unsigned long long w = 0;
#pragma unroll
    for (int k = 0; k < 8; ++k) {
        const int j = (s * 8 + k) * 64 + c8 * 8;
        int4 a = *(const int4*)(row + j);
        int4 b = *(const int4*)(row + j + 4);
        unsigned byte = 0;
        byte |= (a.x > 0) ? 1u   : 0u;
        byte |= (a.y > 0) ? 2u   : 0u;
        byte |= (a.z > 0) ? 4u   : 0u;
        byte |= (a.w > 0) ? 8u   : 0u;
        byte |= (b.x > 0) ? 16u  : 0u;
        byte |= (b.y > 0) ? 32u  : 0u;
        byte |= (b.z > 0) ? 64u  : 0u;
        byte |= (b.w > 0) ? 128u : 0u;
        w |= (unsigned long long)byte << (k * 8);
    }
    g_mask[(size_t)i * 128 + s * 8 + c8] = w;
}

// ---------------- Kernel A: Wh = h@W (stored in B layout), f1, f2 ------------
__global__ void __launch_bounds__(256) wh_kernel(const float* __restrict__ h,
                                                 const float* __restrict__ W,
                                                 const float* __restrict__ a) {
    __shared__ float hs[64][64];
    __shared__ float Ws[64][FOUT];

    const int t  = threadIdx.x;
    const int i0 = blockIdx.x * 64;
    const int tf = t & 31;
    const int ti = t >> 5;

    float acc[8][4];
#pragma unroll
    for (int r = 0; r < 8; ++r)
#pragma unroll
        for (int c = 0; c < 4; ++c) acc[r][c] = 0.f;

    for (int kc = 0; kc < 4; ++kc) {
        __syncthreads();
#pragma unroll
        for (int idx = t; idx < 1024; idx += 256) {
            int row = idx >> 4, c = idx & 15;
            *(float4*)&hs[row][c * 4] =
                *(const float4*)&h[(size_t)(i0 + row) * FIN + kc * 64 + c * 4];
        }
#pragma unroll
        for (int idx = t; idx < 2048; idx += 256) {
            int row = idx >> 5, c = idx & 31;
            *(float4*)&Ws[row][c * 4] =
                *(const float4*)&W[(size_t)(kc * 64 + row) * FOUT + c * 4];
        }
        __syncthreads();
#pragma unroll 8
        for (int k = 0; k < 64; ++k) {
            float4 wv = *(float4*)&Ws[k][tf * 4];
#pragma unroll
            for (int r = 0; r < 8; ++r) {
                float hv = hs[ti * 8 + r][k];
                acc[r][0] += hv * wv.x;
                acc[r][1] += hv * wv.y;
                acc[r][2] += hv * wv.z;
                acc[r][3] += hv * wv.w;
            }
        }
    }

    float4 a1v = *(const float4*)&a[tf * 4];
    float4 a2v = *(const float4*)&a[FOUT + tf * 4];
#pragma unroll
    for (int r = 0; r < 8; ++r) {
        float v1 = acc[r][0] * a1v.x + acc[r][1] * a1v.y + acc[r][2] * a1v.z + acc[r][3] * a1v.w;
        float v2 = acc[r][0] * a2v.x + acc[r][1] * a2v.y + acc[r][2] * a2v.z + acc[r][3] * a2v.w;
#pragma unroll
        for (int off = 16; off > 0; off >>= 1) {
            v1 += __shfl_xor_sync(0xffffffffu, v1, off);
            v2 += __shfl_xor_sync(0xffffffffu, v2, off);
        }
        if (tf == 0) {
            g_f1[i0 + ti * 8 + r] = v1;
            g_f2[i0 + ti * 8 + r] = v2;
        }
    }

    float* base = &g_WhB[(size_t)blockIdx.x * 8192 + ti * 1024];
#pragma unroll
    for (int r = 0; r < 4; ++r) {
#pragma unroll
        for (int c = 0; c < 4; ++c) {
            float2 v;
            v.x = to_tf32(acc[r][c]);
            v.y = to_tf32(acc[r + 4][c]);
            *(float2*)&base[(tf * 4 + c) * 8 + r * 2] = v;
        }
    }
}

// ---------------- Kernel C: warp-specialized fused attention -----------------
// grid 128, block 384 (12 warps): wid 0..7 consumers (warp tile 64x16, full K),
// wid 8..11 producers (build P tiles). 4-stage P ring with full/empty mbarriers.
// B fragments from L2 double-buffered in registers; f2 staged in smem.
__global__ void __launch_bounds__(384, 1) gat_kernel(float* __restrict__ out) {
    extern __shared__ float smem[];
    float* f2s = smem;                                  // 8192 floats
    float* Pst = smem + 8192;                           // NSTAGES * P_FLOATS
    float* Ssh = Pst + NSTAGES * P_FLOATS;              // 64 floats
    const uint32_t bar_base =
        (uint32_t)__cvta_generic_to_shared(Ssh + 64);   // full[4] then empty[4]

    const int t    = threadIdx.x;
    const int lane = t & 31;
    const int wid  = t >> 5;
    const int i0   = blockIdx.x * 64;

    const int wf = wid;               // consumers: 0..7
    const int l4 = lane >> 2;
    const int lm = lane & 3;

    float fragC[4][2][4];
#pragma unroll
    for (int mt = 0; mt < 4; ++mt)
#pragma unroll
        for (int nt = 0; nt < 2; ++nt)
#pragma unroll
            for (int c = 0; c < 4; ++c) fragC[mt][nt][c] = 0.f;

    // stage f2 into smem; init barriers
    for (int idx = t; idx < NN / 4; idx += 384)
        *(float4*)&f2s[idx * 4] = *(const float4*)&g_f2[idx * 4];
    if (t == 0) {
#pragma unroll
        for (int s = 0; s < NSTAGES; ++s) {
            MBAR_INIT(bar_base + s * 8, 128);        // full: 128 producer threads
            MBAR_INIT(bar_base + 32 + s * 8, 256);   // empty: 256 consumer threads
        }
    }
    __syncthreads();

    if (wid >= 8) {
        // ======================= PRODUCERS ==================================
        const int pt   = (wid - 8) * 32 + lane;   // 0..127
        const int ii   = pt >> 1;                 // row in tile
        const int half = pt & 1;                  // 32-col half
        const float f1i = g_f1[i0 + ii];
        const unsigned long long* mrow =
            g_mask + (size_t)(i0 + ii) * 128 + half * 4;
        float sacc = 0.f;
        unsigned long long w0 = 0, w1 = 0, w2 = 0, w3 = 0;
        int stage = 0, phase = 1;

#pragma unroll 1
        for (int jt = 0; jt < NTILES; ++jt) {
            if ((jt & 7) == 0) {
                const unsigned long long* mp = mrow + (size_t)(jt >> 3) * 8;
                ulonglong2 ma = *(const ulonglong2*)mp;
                ulonglong2 mc = *(const ulonglong2*)(mp + 2);
                w0 = ma.x; w1 = ma.y; w2 = mc.x; w3 = mc.y;
            }
            const int sh = (jt & 7) * 8;
            unsigned mby[4];
            mby[0] = (unsigned)(w0 >> sh) & 0xffu;
            mby[1] = (unsigned)(w1 >> sh) & 0xffu;
            mby[2] = (unsigned)(w2 >> sh) & 0xffu;
            mby[3] = (unsigned)(w3 >> sh) & 0xffu;

            MBAR_WAIT(bar_base + 32 + stage * 8, phase);   // wait empty

            float* pd = Pst + stage * P_FLOATS + ii * PB_STRIDE + half * 32;
            const float* f2p = f2s + jt * 64 + half * 32;
#pragma unroll
            for (int q = 0; q < 4; ++q) {
                const unsigned mb = mby[q];
                float4 fa = *(const float4*)(f2p + q * 8);
                float4 fb = *(const float4*)(f2p + q * 8 + 4);
                float4 pva, pvb;
                pva.x = (mb & 1u)   ? to_tf32(lrelu_exp(f1i + fa.x)) : 0.f;
                pva.y = (mb & 2u)   ? to_tf32(lrelu_exp(f1i + fa.y)) : 0.f;
                pva.z = (mb & 4u)   ? to_tf32(lrelu_exp(f1i + fa.z)) : 0.f;
                pva.w = (mb & 8u)   ? to_tf32(lrelu_exp(f1i + fa.w)) : 0.f;
                pvb.x = (mb & 16u)  ? to_tf32(lrelu_exp(f1i + fb.x)) : 0.f;
                pvb.y = (mb & 32u)  ? to_tf32(lrelu_exp(f1i + fb.y)) : 0.f;
                pvb.z = (mb & 64u)  ? to_tf32(lrelu_exp(f1i + fb.z)) : 0.f;
                pvb.w = (mb & 128u) ? to_tf32(lrelu_exp(f1i + fb.w)) : 0.f;
                // permuted slots [c0,c4,c1,c5,c2,c6,c3,c7]
                float4 q0 = make_float4(pva.x, pvb.x, pva.y, pvb.y);
                float4 q1 = make_float4(pva.z, pvb.z, pva.w, pvb.w);
                *(float4*)(pd + q * 8)     = q0;
                *(float4*)(pd + q * 8 + 4) = q1;
                sacc += pva.x + pva.y + pva.z + pva.w
                      + pvb.x + pvb.y + pvb.z + pvb.w;
            }
            MBAR_ARRIVE(bar_base + stage * 8);             // signal full
            if (++stage == NSTAGES) { stage = 0; phase ^= 1; }
        }
        sacc += __shfl_xor_sync(0xffffffffu, sacc, 1);
        if (half == 0) Ssh[ii] = sacc;
    } else {
        // ======================= CONSUMERS ==================================
        const float* bwarp = g_WhB + (wf * 16 + l4) * 8 + lm * 2;
        float2 bcur[8][2], bnxt[8][2];
#pragma unroll
        for (int k2 = 0; k2 < 8; ++k2)
#pragma unroll
            for (int nt = 0; nt < 2; ++nt)
                bcur[k2][nt] = *(const float2*)(bwarp + k2 * 1024 + nt * 64);

        int stage = 0, phase = 0;
#pragma unroll 1
        for (int jt = 0; jt < NTILES; ++jt) {
            if (jt + 1 < NTILES) {
                const float* bt = bwarp + (size_t)(jt + 1) * 8192;
#pragma unroll
                for (int k2 = 0; k2 < 8; ++k2)
#pragma unroll
                    for (int nt = 0; nt < 2; ++nt)
                        bnxt[k2][nt] = *(const float2*)(bt + k2 * 1024 + nt * 64);
            }

            MBAR_WAIT(bar_base + stage * 8, phase);        // wait full

            const float* Pc    = Pst + stage * P_FLOATS;
            const float* abase = Pc + l4 * PB_STRIDE + lm * 2;
#pragma unroll
            for (int k2 = 0; k2 < 8; ++k2) {
                uint32_t a0[4], a1[4], a2[4], a3[4];
#pragma unroll
                for (int mt = 0; mt < 4; ++mt) {
                    const float* pAm = abase + mt * 16 * PB_STRIDE + k2 * 8;
                    float2 lo = *(const float2*)pAm;
                    float2 hi = *(const float2*)(pAm + 8 * PB_STRIDE);
                    a0[mt] = __float_as_uint(lo.x);
                    a2[mt] = __float_as_uint(lo.y);
                    a1[mt] = __float_as_uint(hi.x);
                    a3[mt] = __float_as_uint(hi.y);
                }
#pragma unroll
                for (int nt = 0; nt < 2; ++nt) {
                    uint32_t b0 = __float_as_uint(bcur[k2][nt].x);
                    uint32_t b1 = __float_as_uint(bcur[k2][nt].y);
#pragma unroll
                    for (int mt = 0; mt < 4; ++mt)
                        mma_tf32(fragC[mt][nt], a0[mt], a1[mt], a2[mt], a3[mt], b0, b1);
                }
            }
            MBAR_ARRIVE(bar_base + 32 + stage * 8);        // signal empty
            if (++stage == NSTAGES) { stage = 0; phase ^= 1; }
#pragma unroll
            for (int k2 = 0; k2 < 8; ++k2) {
                bcur[k2][0] = bnxt[k2][0];
                bcur[k2][1] = bnxt[k2][1];
            }
        }
    }

    __syncthreads();   // Ssh visible; all ring traffic done

    if (wid < 8) {
        // ---- epilogue: normalize, elu, store (no k-split -> no reduction) --
#pragma unroll
        for (int mt = 0; mt < 4; ++mt) {
            const int row0 = mt * 16 + l4;
            const float s0 = 1.f / Ssh[row0];
            const float s1 = 1.f / Ssh[row0 + 8];
#pragma unroll
            for (int nt = 0; nt < 2; ++nt) {
                float x0 = fragC[mt][nt][0] * s0;
                float x1 = fragC[mt][nt][1] * s0;
                float x2 = fragC[mt][nt][2] * s1;
                float x3 = fragC[mt][nt][3] * s1;
                const int gcol = wf * 16 + nt * 8 + lm * 2;
                const size_t o0 = (size_t)(i0 + row0) * FOUT + gcol;
                const size_t o1 = (size_t)(i0 + row0 + 8) * FOUT + gcol;
                out[o0]     = (x0 > 0.f) ? x0 : expm1f(x0);
                out[o0 + 1] = (x1 > 0.f) ? x1 : expm1f(x1);
                out[o1]     = (x2 > 0.f) ? x2 : expm1f(x2);
                out[o1 + 1] = (x3 > 0.f) ? x3 : expm1f(x3);
            }
        }
    }
}

// ---------------- launch ------------------------------------------------------
extern "C" void kernel_launch(void* const* d_in, const int* in_sizes, int n_in,
                              void* d_out, int out_size) {
    const float* h   = (const float*)d_in[0];
    const int*   adj = (const int*)d_in[1];
    const float* W   = (const float*)d_in[2];
    const float* a   = (const float*)d_in[3];
    float*       out = (float*)d_out;

    mask_kernel<<<NN, 128>>>(adj);
    wh_kernel<<<NN / 64, 256>>>(h, W, a);

    // f2(8192) + P ring(4*4608) + Ssh(64) floats + 64B barriers + pad
    const int smem_bytes = (8192 + NSTAGES * P_FLOATS + 64) * sizeof(float) + 128;
    cudaFuncSetAttribute(gat_kernel, cudaFuncAttributeMaxDynamicSharedMemorySize, smem_bytes);
    gat_kernel<<<NN / 64, 384, smem_bytes>>>(out);
}

// round 11
// speedup vs baseline: 1.5169x; 1.5169x over previous
#include <cuda_runtime.h>
#include <cstdint>
#include <cstddef>

#define NN   8192
#define FIN  256
#define FOUT 128
#define ALPHA_SLOPE 0.2f

#define PB_STRIDE 72
#define P_FLOATS  (64 * PB_STRIDE)     // 4608 per stage
#define NT_HALF   64                   // j-tiles per half
#define F2S_FLOATS 4096                // f2 slice per half

// ---------------- scratch (device globals: no allocation allowed) ------------
// g_WhB: Wh pre-staged in MMA-B fragment layout per 64-row j-tile:
//   addr = tile*8192 + kt*1024 + f*8 + (kl&3)*2 + (kl>>2),  row = tile*64+kt*8+kl
__device__ float g_WhB[(size_t)NN * FOUT];
__device__ float g_f1[NN];
__device__ float g_f2[NN];
// bitmask of adj>0: word index = row*128 + s*8 + c8  (s = jt>>3), byte jt&7,
// bit b = column j = jt*64 + c8*8 + b.
__device__ unsigned long long g_mask[(size_t)NN * 128];
// partial results per j-half
__device__ float g_pacc[2][(size_t)NN * FOUT];
__device__ float g_ps[2][NN];

// ---------------- helpers ----------------------------------------------------
__device__ __forceinline__ float to_tf32(float x) {
    uint32_t u;
    asm("cvt.rna.tf32.f32 %0, %1;" : "=r"(u) : "f"(x));
    return __uint_as_float(u);
}

__device__ __forceinline__ void mma_tf32(float* c,
                                         uint32_t a0, uint32_t a1, uint32_t a2, uint32_t a3,
                                         uint32_t b0, uint32_t b1) {
    asm volatile(
        "mma.sync.aligned.m16n8k8.row.col.f32.tf32.tf32.f32 "
        "{%0,%1,%2,%3}, {%4,%5,%6,%7}, {%8,%9}, {%0,%1,%2,%3};\n"
        : "+f"(c[0]), "+f"(c[1]), "+f"(c[2]), "+f"(c[3])
        : "r"(a0), "r"(a1), "r"(a2), "r"(a3), "r"(b0), "r"(b1));
}

__device__ __forceinline__ float lrelu_exp(float s) {
    s = fmaxf(s, ALPHA_SLOPE * s);
    return __expf(s);
}

// ---------------- Kernel M: adj -> bitmask -----------------------------------
__global__ void __launch_bounds__(128) mask_kernel(const int* __restrict__ adj) {
    const int i  = blockIdx.x;
    const int t  = threadIdx.x;
    const int c8 = t & 7;
    const int s  = t >> 3;

    const int* row = adj + (size_t)i * NN;
    unsigned long long w = 0;
#pragma unroll
    for (int k = 0; k < 8; ++k) {
        const int j = (s * 8 + k) * 64 + c8 * 8;
        int4 a = *(const int4*)(row + j);
        int4 b = *(const int4*)(row + j + 4);
        unsigned byte = 0;
        byte |= (a.x > 0) ? 1u   : 0u;
        byte |= (a.y > 0) ? 2u   : 0u;
        byte |= (a.z > 0) ? 4u   : 0u;
        byte |= (a.w > 0) ? 8u   : 0u;
        byte |= (b.x > 0) ? 16u  : 0u;
        byte |= (b.y > 0) ? 32u  : 0u;
        byte |= (b.z > 0) ? 64u  : 0u;
        byte |= (b.w > 0) ? 128u : 0u;
        w |= (unsigned long long)byte << (k * 8);
    }
    g_mask[(size_t)i * 128 + s * 8 + c8] = w;
}

// ---------------- Kernel A: Wh = h@W (stored in B layout), f1, f2 ------------
__global__ void __launch_bounds__(256) wh_kernel(const float* __restrict__ h,
                                                 const float* __restrict__ W,
                                                 const float* __restrict__ a) {
    __shared__ float hs[64][64];
    __shared__ float Ws[64][FOUT];

    const int t  = threadIdx.x;
    const int i0 = blockIdx.x * 64;
    const int tf = t & 31;
    const int ti = t >> 5;

    float acc[8][4];
#pragma unroll
    for (int r = 0; r < 8; ++r)
#pragma unroll
        for (int c = 0; c < 4; ++c) acc[r][c] = 0.f;

    for (int kc = 0; kc < 4; ++kc) {
        __syncthreads();
#pragma unroll
        for (int idx = t; idx < 1024; idx += 256) {
            int row = idx >> 4, c = idx & 15;
            *(float4*)&hs[row][c * 4] =
                *(const float4*)&h[(size_t)(i0 + row) * FIN + kc * 64 + c * 4];
        }
#pragma unroll
        for (int idx = t; idx < 2048; idx += 256) {
            int row = idx >> 5, c = idx & 31;
            *(float4*)&Ws[row][c * 4] =
                *(const float4*)&W[(size_t)(kc * 64 + row) * FOUT + c * 4];
        }
        __syncthreads();
#pragma unroll 8
        for (int k = 0; k < 64; ++k) {
            float4 wv = *(float4*)&Ws[k][tf * 4];
#pragma unroll
            for (int r = 0; r < 8; ++r) {
                float hv = hs[ti * 8 + r][k];
                acc[r][0] += hv * wv.x;
                acc[r][1] += hv * wv.y;
                acc[r][2] += hv * wv.z;
                acc[r][3] += hv * wv.w;
            }
        }
    }

    float4 a1v = *(const float4*)&a[tf * 4];
    float4 a2v = *(const float4*)&a[FOUT + tf * 4];
#pragma unroll
    for (int r = 0; r < 8; ++r) {
        float v1 = acc[r][0] * a1v.x + acc[r][1] * a1v.y + acc[r][2] * a1v.z + acc[r][3] * a1v.w;
        float v2 = acc[r][0] * a2v.x + acc[r][1] * a2v.y + acc[r][2] * a2v.z + acc[r][3] * a2v.w;
#pragma unroll
        for (int off = 16; off > 0; off >>= 1) {
            v1 += __shfl_xor_sync(0xffffffffu, v1, off);
            v2 += __shfl_xor_sync(0xffffffffu, v2, off);
        }
        if (tf == 0) {
            g_f1[i0 + ti * 8 + r] = v1;
            g_f2[i0 + ti * 8 + r] = v2;
        }
    }

    float* base = &g_WhB[(size_t)blockIdx.x * 8192 + ti * 1024];
#pragma unroll
    for (int r = 0; r < 4; ++r) {
#pragma unroll
        for (int c = 0; c < 4; ++c) {
            float2 v;
            v.x = to_tf32(acc[r][c]);
            v.y = to_tf32(acc[r + 4][c]);
            *(float2*)&base[(tf * 4 + c) * 8 + r * 2] = v;
        }
    }
}

// ---------------- Kernel C: fused masked attention (partial over j-half) -----
// grid (128, 2), block 256 (8 warps), 2 blocks/SM. Block tile 64(i) x 128(f),
// j-tiles of 64 within half h. Warp tile 64(M) x 16(N), full K (no k-split).
// All threads build P (row = t>>2, 16 cols each); all 8 warps do MMA.
// B fragments direct from L2; f2 half staged in smem; adj via bitmask.
__global__ void __launch_bounds__(256, 2) gat_kernel() {
    extern __shared__ float smem[];
    float* f2s = smem;                          // 4096 floats (this half)
    float* Pst = smem + F2S_FLOATS;             // 2 * P_FLOATS

    const int t    = threadIdx.x;
    const int lane = t & 31;
    const int wid  = t >> 5;
    const int i0   = blockIdx.x * 64;
    const int h    = blockIdx.y;

    const int ii  = t >> 2;           // P producer row (0..63)
    const int c16 = t & 3;            // P producer 16-col chunk

    const int wf = wid;               // 0..7 (N: 16 cols)
    const int l4 = lane >> 2;
    const int lm = lane & 3;

    const float f1i = g_f1[i0 + ii];
    float sacc = 0.f;

    float fragC[4][2][4];
#pragma unroll
    for (int mt = 0; mt < 4; ++mt)
#pragma unroll
        for (int nt = 0; nt < 2; ++nt)
#pragma unroll
            for (int c = 0; c < 4; ++c) fragC[mt][nt][c] = 0.f;

    // stage this half's f2 into smem
    for (int idx = t; idx < F2S_FLOATS / 4; idx += 256)
        *(float4*)&f2s[idx * 4] =
            *(const float4*)&g_f2[h * F2S_FLOATS + idx * 4];

    // invariant addresses
    const unsigned long long* mrow =
        g_mask + (size_t)(i0 + ii) * 128 + c16 * 2;
    const float* bwarp = g_WhB + (wf * 16 + l4) * 8 + lm * 2;
    float* pdst[2];
    pdst[0] = &Pst[ii * PB_STRIDE + c16 * 16];
    pdst[1] = &Pst[P_FLOATS + ii * PB_STRIDE + c16 * 16];

    unsigned long long mw0 = 0, mw1 = 0;
    unsigned mb0, mb1;

// P written permuted per 8-col group: col q -> slot (q&3)*2 + (q>>2)
// slots = [c0,c4,c1,c5,c2,c6,c3,c7]; A-frag (col lm, lm+4) is one float2.
#define STORE_P(ST, JT)                                                     \
    do {                                                                    \
        float* pd = pdst[ST];                                               \
        const float* f2p = f2s + (JT) * 64 + c16 * 16;                      \
        _Pragma("unroll")                                                   \
        for (int e = 0; e < 2; ++e) {                                       \
            const unsigned mb = e ? mb1 : mb0;                              \
            float4 fa = *(const float4*)(f2p + e * 8);                      \
            float4 fb = *(const float4*)(f2p + e * 8 + 4);                  \
            float4 pva, pvb;                                                \
            pva.x = (mb & 1u)   ? to_tf32(lrelu_exp(f1i + fa.x)) : 0.f;     \
            pva.y = (mb & 2u)   ? to_tf32(lrelu_exp(f1i + fa.y)) : 0.f;     \
            pva.z = (mb & 4u)   ? to_tf32(lrelu_exp(f1i + fa.z)) : 0.f;     \
            pva.w = (mb & 8u)   ? to_tf32(lrelu_exp(f1i + fa.w)) : 0.f;     \
            pvb.x = (mb & 16u)  ? to_tf32(lrelu_exp(f1i + fb.x)) : 0.f;     \
            pvb.y = (mb & 32u)  ? to_tf32(lrelu_exp(f1i + fb.y)) : 0.f;     \
            pvb.z = (mb & 64u)  ? to_tf32(lrelu_exp(f1i + fb.z)) : 0.f;     \
            pvb.w = (mb & 128u) ? to_tf32(lrelu_exp(f1i + fb.w)) : 0.f;     \
            float4 q0 = make_float4(pva.x, pvb.x, pva.y, pvb.y);            \
            float4 q1 = make_float4(pva.z, pvb.z, pva.w, pvb.w);            \
            *(float4*)(pd + e * 8)     = q0;                                \
            *(float4*)(pd + e * 8 + 4) = q1;                                \
            sacc += pva.x + pva.y + pva.z + pva.w                           \
                  + pvb.x + pvb.y + pvb.z + pvb.w;                          \
        }                                                                   \
    } while (0)

#define LOAD_MASK(JT)                                                       \
    do {                                                                    \
        if (((JT) & 7) == 0) {                                              \
            ulonglong2 mm = *(const ulonglong2*)(mrow +                     \
                (size_t)(h * 8 + ((JT) >> 3)) * 8);                         \
            mw0 = mm.x; mw1 = mm.y;                                         \
        }                                                                   \
        const int sh = ((JT) & 7) * 8;                                      \
        mb0 = (unsigned)(mw0 >> sh) & 0xffu;                                \
        mb1 = (unsigned)(mw1 >> sh) & 0xffu;                                \
    } while (0)

    __syncthreads();        // f2s staged
    LOAD_MASK(0);
    STORE_P(0, 0);
    __syncthreads();

#pragma unroll 1
    for (int jt = 0; jt < NT_HALF; ++jt) {
        const int cur = jt & 1;
        const bool has_next = (jt + 1) < NT_HALF;
        if (has_next) LOAD_MASK(jt + 1);

        // ---- B fragments for this tile from L2 (16 x LDG.64) ---------------
        const float* bt = bwarp + (size_t)(h * NT_HALF + jt) * 8192;
        float2 bb[8][2];
#pragma unroll
        for (int k2 = 0; k2 < 8; ++k2)
#pragma unroll
            for (int nt = 0; nt < 2; ++nt)
                bb[k2][nt] = *(const float2*)(bt + k2 * 1024 + nt * 64);

        // ---- A fragments from smem + MMA (full K) --------------------------
        const float* Pc    = Pst + cur * P_FLOATS;
        const float* abase = Pc + l4 * PB_STRIDE + lm * 2;
#pragma unroll
        for (int k2 = 0; k2 < 8; ++k2) {
            uint32_t a0[4], a1[4], a2[4], a3[4];
#pragma unroll
            for (int mt = 0; mt < 4; ++mt) {
                const float* pAm = abase + mt * 16 * PB_STRIDE + k2 * 8;
                float2 lo = *(const float2*)pAm;
                float2 hi = *(const float2*)(pAm + 8 * PB_STRIDE);
                a0[mt] = __float_as_uint(lo.x);
                a2[mt] = __float_as_uint(lo.y);
                a1[mt] = __float_as_uint(hi.x);
                a3[mt] = __float_as_uint(hi.y);
            }
#pragma unroll
            for (int nt = 0; nt < 2; ++nt) {
                uint32_t b0 = __float_as_uint(bb[k2][nt].x);
                uint32_t b1 = __float_as_uint(bb[k2][nt].y);
#pragma unroll
                for (int mt = 0; mt < 4; ++mt)
                    mma_tf32(fragC[mt][nt], a0[mt], a1[mt], a2[mt], a3[mt], b0, b1);
            }
        }

        if (has_next) STORE_P(cur ^ 1, jt + 1);
        __syncthreads();
    }

    // ---- partial row sums: reduce across the 4 producers of each row --------
    sacc += __shfl_xor_sync(0xffffffffu, sacc, 1);
    sacc += __shfl_xor_sync(0xffffffffu, sacc, 2);
    if (c16 == 0) g_ps[h][i0 + ii] = sacc;

    // ---- partial accumulators straight to gmem (no normalize here) ----------
    float* pout = g_pacc[h];
#pragma unroll
    for (int mt = 0; mt < 4; ++mt) {
        const int row0 = mt * 16 + l4;
#pragma unroll
        for (int nt = 0; nt < 2; ++nt) {
            const int gcol = wf * 16 + nt * 8 + lm * 2;
            float2 v0, v1;
            v0.x = fragC[mt][nt][0];
            v0.y = fragC[mt][nt][1];
            v1.x = fragC[mt][nt][2];
            v1.y = fragC[mt][nt][3];
            *(float2*)&pout[(size_t)(i0 + row0) * FOUT + gcol]     = v0;
            *(float2*)&pout[(size_t)(i0 + row0 + 8) * FOUT + gcol] = v1;
        }
    }
#undef STORE_P
#undef LOAD_MASK
}

// ---------------- Kernel D: combine halves, normalize, elu -------------------
__global__ void __launch_bounds__(256) combine_kernel(float* __restrict__ out) {
    const int idx = blockIdx.x * 256 + threadIdx.x;   // 262144 float4 slots
    const int row = idx >> 5;
    const int c4  = (idx & 31) << 2;
    const size_t off = (size_t)row * FOUT + c4;
    float4 a0 = *(const float4*)&g_pacc[0][off];
    float4 a1 = *(const float4*)&g_pacc[1][off];
    const float s = 1.f / (g_ps[0][row] + g_ps[1][row]);
    float4 o;
    o.x = (a0.x + a1.x) * s;
    o.y = (a0.y + a1.y) * s;
    o.z = (a0.z + a1.z) * s;
    o.w = (a0.w + a1.w) * s;
    o.x = (o.x > 0.f) ? o.x : expm1f(o.x);
    o.y = (o.y > 0.f) ? o.y : expm1f(o.y);
    o.z = (o.z > 0.f) ? o.z : expm1f(o.z);
    o.w = (o.w > 0.f) ? o.w : expm1f(o.w);
    *(float4*)&out[off] = o;
}

// ---------------- launch ------------------------------------------------------
extern "C" void kernel_launch(void* const* d_in, const int* in_sizes, int n_in,
                              void* d_out, int out_size) {
    const float* h   = (const float*)d_in[0];
    const int*   adj = (const int*)d_in[1];
    const float* W   = (const float*)d_in[2];
    const float* a   = (const float*)d_in[3];
    float*       out = (float*)d_out;

    mask_kernel<<<NN, 128>>>(adj);
    wh_kernel<<<NN / 64, 256>>>(h, W, a);

    const int smem_bytes = (F2S_FLOATS + 2 * P_FLOATS) * sizeof(float); // 53248
    cudaFuncSetAttribute(gat_kernel, cudaFuncAttributeMaxDynamicSharedMemorySize, smem_bytes);
    gat_kernel<<<dim3(NN / 64, 2), 256, smem_bytes>>>();

    combine_kernel<<<(NN * FOUT / 4) / 256, 256>>>(out);
}

// round 12
// speedup vs baseline: 1.6758x; 1.1047x over previous
#include <cuda_runtime.h>
#include <cstdint>
#include <cstddef>

#define NN   8192
#define FIN  256
#define FOUT 128
#define ALPHA_SLOPE 0.2f

#define PB_STRIDE 72
#define P_FLOATS  (64 * PB_STRIDE)     // 4608 per stage
#define NT_HALF   64                   // j-tiles per half
#define F2S_FLOATS 4096                // f2 slice per half

// ---------------- scratch (device globals: no allocation allowed) ------------
// g_WhB: Wh pre-staged in MMA-B fragment layout per 64-row j-tile:
//   addr = tile*8192 + kt*1024 + f*8 + (kl&3)*2 + (kl>>2),  row = tile*64+kt*8+kl
__device__ float g_WhB[(size_t)NN * FOUT];
__device__ float g_f1[NN];
__device__ float g_f2[NN];
// partial results per j-half
__device__ float g_pacc[2][(size_t)NN * FOUT];
__device__ float g_ps[2][NN];

// ---------------- helpers ----------------------------------------------------
__device__ __forceinline__ float to_tf32(float x) {
    uint32_t u;
    asm("cvt.rna.tf32.f32 %0, %1;" : "=r"(u) : "f"(x));
    return __uint_as_float(u);
}

__device__ __forceinline__ void mma_tf32(float* c,
                                         uint32_t a0, uint32_t a1, uint32_t a2, uint32_t a3,
                                         uint32_t b0, uint32_t b1) {
    asm volatile(
        "mma.sync.aligned.m16n8k8.row.col.f32.tf32.tf32.f32 "
        "{%0,%1,%2,%3}, {%4,%5,%6,%7}, {%8,%9}, {%0,%1,%2,%3};\n"
        : "+f"(c[0]), "+f"(c[1]), "+f"(c[2]), "+f"(c[3])
        : "r"(a0), "r"(a1), "r"(a2), "r"(a3), "r"(b0), "r"(b1));
}

__device__ __forceinline__ float lrelu_exp(float s) {
    s = fmaxf(s, ALPHA_SLOPE * s);
    return __expf(s);
}

__device__ __forceinline__ int4 ldcs4(const int4* p) {
    return __ldcs(p);   // streaming: adj is read exactly once
}

// ---------------- Kernel A: Wh = h@W (stored in B layout), f1, f2 ------------
__global__ void __launch_bounds__(256) wh_kernel(const float* __restrict__ h,
                                                 const float* __restrict__ W,
                                                 const float* __restrict__ a) {
    __shared__ float hs[64][64];
    __shared__ float Ws[64][FOUT];

    const int t  = threadIdx.x;
    const int i0 = blockIdx.x * 64;
    const int tf = t & 31;
    const int ti = t >> 5;

    float acc[8][4];
#pragma unroll
    for (int r = 0; r < 8; ++r)
#pragma unroll
        for (int c = 0; c < 4; ++c) acc[r][c] = 0.f;

    for (int kc = 0; kc < 4; ++kc) {
        __syncthreads();
#pragma unroll
        for (int idx = t; idx < 1024; idx += 256) {
            int row = idx >> 4, c = idx & 15;
            *(float4*)&hs[row][c * 4] =
                *(const float4*)&h[(size_t)(i0 + row) * FIN + kc * 64 + c * 4];
        }
#pragma unroll
        for (int idx = t; idx < 2048; idx += 256) {
            int row = idx >> 5, c = idx & 31;
            *(float4*)&Ws[row][c * 4] =
                *(const float4*)&W[(size_t)(kc * 64 + row) * FOUT + c * 4];
        }
        __syncthreads();
#pragma unroll 8
        for (int k = 0; k < 64; ++k) {
            float4 wv = *(float4*)&Ws[k][tf * 4];
#pragma unroll
            for (int r = 0; r < 8; ++r) {
                float hv = hs[ti * 8 + r][k];
                acc[r][0] += hv * wv.x;
                acc[r][1] += hv * wv.y;
                acc[r][2] += hv * wv.z;
                acc[r][3] += hv * wv.w;
            }
        }
    }

    float4 a1v = *(const float4*)&a[tf * 4];
    float4 a2v = *(const float4*)&a[FOUT + tf * 4];
#pragma unroll
    for (int r = 0; r < 8; ++r) {
        float v1 = acc[r][0] * a1v.x + acc[r][1] * a1v.y + acc[r][2] * a1v.z + acc[r][3] * a1v.w;
        float v2 = acc[r][0] * a2v.x + acc[r][1] * a2v.y + acc[r][2] * a2v.z + acc[r][3] * a2v.w;
#pragma unroll
        for (int off = 16; off > 0; off >>= 1) {
            v1 += __shfl_xor_sync(0xffffffffu, v1, off);
            v2 += __shfl_xor_sync(0xffffffffu, v2, off);
        }
        if (tf == 0) {
            g_f1[i0 + ti * 8 + r] = v1;
            g_f2[i0 + ti * 8 + r] = v2;
        }
    }

    float* base = &g_WhB[(size_t)blockIdx.x * 8192 + ti * 1024];
#pragma unroll
    for (int r = 0; r < 4; ++r) {
#pragma unroll
        for (int c = 0; c < 4; ++c) {
            float2 v;
            v.x = to_tf32(acc[r][c]);
            v.y = to_tf32(acc[r + 4][c]);
            *(float2*)&base[(tf * 4 + c) * 8 + r * 2] = v;
        }
    }
}

// ---------------- Kernel C: fused masked attention (partial over j-half) -----
// grid (128, 2), block 256 (8 warps), 2 blocks/SM. Block tile 64(i) x 128(f),
// j-tiles of 64 within half h. Warp tile 64(M) x 16(N), full K.
// All threads build P (row = t>>2, 16 cols each); all 8 warps do MMA.
// adj read inline via streaming LDG (no bitmask pass); B fragments direct from
// L2; f2 half staged in smem.
__global__ void __launch_bounds__(256, 2) gat_kernel(const int* __restrict__ adj) {
    extern __shared__ float smem[];
    float* f2s = smem;                          // 4096 floats (this half)
    float* Pst = smem + F2S_FLOATS;             // 2 * P_FLOATS

    const int t    = threadIdx.x;
    const int lane = t & 31;
    const int wid  = t >> 5;
    const int i0   = blockIdx.x * 64;
    const int h    = blockIdx.y;

    const int ii  = t >> 2;           // P producer row (0..63)
    const int c16 = t & 3;            // P producer 16-col chunk

    const int wf = wid;               // 0..7 (N: 16 cols)
    const int l4 = lane >> 2;
    const int lm = lane & 3;

    const float f1i = g_f1[i0 + ii];
    float sacc = 0.f;

    float fragC[4][2][4];
#pragma unroll
    for (int mt = 0; mt < 4; ++mt)
#pragma unroll
        for (int nt = 0; nt < 2; ++nt)
#pragma unroll
            for (int c = 0; c < 4; ++c) fragC[mt][nt][c] = 0.f;

    // stage this half's f2 into smem
    for (int idx = t; idx < F2S_FLOATS / 4; idx += 256)
        *(float4*)&f2s[idx * 4] =
            *(const float4*)&g_f2[h * F2S_FLOATS + idx * 4];

    // invariant addresses
    const int4* adj_base = (const int4*)(adj + (size_t)(i0 + ii) * NN
                                         + h * F2S_FLOATS + c16 * 16);
    const float* bwarp = g_WhB + (wf * 16 + l4) * 8 + lm * 2;
    float* pdst[2];
    pdst[0] = &Pst[ii * PB_STRIDE + c16 * 16];
    pdst[1] = &Pst[P_FLOATS + ii * PB_STRIDE + c16 * 16];

    int4 adjA, adjB, adjC, adjD;

#define LOAD_ADJ(JT)                                                        \
    do {                                                                    \
        const int4* ap = adj_base + (size_t)(JT) * 16;                      \
        adjA = ldcs4(ap);                                                   \
        adjB = ldcs4(ap + 1);                                               \
        adjC = ldcs4(ap + 2);                                               \
        adjD = ldcs4(ap + 3);                                               \
    } while (0)

// P written permuted per 8-col group: col q -> slot (q&3)*2 + (q>>2)
// slots = [c0,c4,c1,c5,c2,c6,c3,c7]; A-frag (col lm, lm+4) is one float2.
#define STORE_P(ST, JT)                                                     \
    do {                                                                    \
        float* pd = pdst[ST];                                               \
        const float* f2p = f2s + (JT) * 64 + c16 * 16;                      \
        _Pragma("unroll")                                                   \
        for (int e = 0; e < 2; ++e) {                                       \
            const int4 ma = e ? adjC : adjA;                                \
            const int4 mbv = e ? adjD : adjB;                               \
            float4 fa = *(const float4*)(f2p + e * 8);                      \
            float4 fb = *(const float4*)(f2p + e * 8 + 4);                  \
            float4 pva, pvb;                                                \
            pva.x = (ma.x > 0)  ? to_tf32(lrelu_exp(f1i + fa.x)) : 0.f;     \
            pva.y = (ma.y > 0)  ? to_tf32(lrelu_exp(f1i + fa.y)) : 0.f;     \
            pva.z = (ma.z > 0)  ? to_tf32(lrelu_exp(f1i + fa.z)) : 0.f;     \
            pva.w = (ma.w > 0)  ? to_tf32(lrelu_exp(f1i + fa.w)) : 0.f;     \
            pvb.x = (mbv.x > 0) ? to_tf32(lrelu_exp(f1i + fb.x)) : 0.f;     \
            pvb.y = (mbv.y > 0) ? to_tf32(lrelu_exp(f1i + fb.y)) : 0.f;     \
            pvb.z = (mbv.z > 0) ? to_tf32(lrelu_exp(f1i + fb.z)) : 0.f;     \
            pvb.w = (mbv.w > 0) ? to_tf32(lrelu_exp(f1i + fb.w)) : 0.f;     \
            float4 q0 = make_float4(pva.x, pvb.x, pva.y, pvb.y);            \
            float4 q1 = make_float4(pva.z, pvb.z, pva.w, pvb.w);            \
            *(float4*)(pd + e * 8)     = q0;                                \
            *(float4*)(pd + e * 8 + 4) = q1;                                \
            sacc += pva.x + pva.y + pva.z + pva.w                           \
                  + pvb.x + pvb.y + pvb.z + pvb.w;                          \
        }                                                                   \
    } while (0)

    LOAD_ADJ(0);
    __syncthreads();        // f2s staged
    STORE_P(0, 0);
    __syncthreads();

#pragma unroll 1
    for (int jt = 0; jt < NT_HALF; ++jt) {
        const int cur = jt & 1;
        const bool has_next = (jt + 1) < NT_HALF;
        if (has_next) LOAD_ADJ(jt + 1);

        // ---- B fragments for this tile from L2 (16 x LDG.64) ---------------
        const float* bt = bwarp + (size_t)(h * NT_HALF + jt) * 8192;
        float2 bb[8][2];
#pragma unroll
        for (int k2 = 0; k2 < 8; ++k2)
#pragma unroll
            for (int nt = 0; nt < 2; ++nt)
                bb[k2][nt] = *(const float2*)(bt + k2 * 1024 + nt * 64);

        // ---- A fragments from smem + MMA (full K) --------------------------
        const float* Pc    = Pst + cur * P_FLOATS;
        const float* abase = Pc + l4 * PB_STRIDE + lm * 2;
#pragma unroll
        for (int k2 = 0; k2 < 8; ++k2) {
            uint32_t a0[4], a1[4], a2[4], a3[4];
#pragma unroll
            for (int mt = 0; mt < 4; ++mt) {
                const float* pAm = abase + mt * 16 * PB_STRIDE + k2 * 8;
                float2 lo = *(const float2*)pAm;
                float2 hi = *(const float2*)(pAm + 8 * PB_STRIDE);
                a0[mt] = __float_as_uint(lo.x);
                a2[mt] = __float_as_uint(lo.y);
                a1[mt] = __float_as_uint(hi.x);
                a3[mt] = __float_as_uint(hi.y);
            }
#pragma unroll
            for (int nt = 0; nt < 2; ++nt) {
                uint32_t b0 = __float_as_uint(bb[k2][nt].x);
                uint32_t b1 = __float_as_uint(bb[k2][nt].y);
#pragma unroll
                for (int mt = 0; mt < 4; ++mt)
                    mma_tf32(fragC[mt][nt], a0[mt], a1[mt], a2[mt], a3[mt], b0, b1);
            }
        }

        if (has_next) STORE_P(cur ^ 1, jt + 1);
        __syncthreads();
    }

    // ---- partial row sums: reduce across the 4 producers of each row --------
    sacc += __shfl_xor_sync(0xffffffffu, sacc, 1);
    sacc += __shfl_xor_sync(0xffffffffu, sacc, 2);
    if (c16 == 0) g_ps[h][i0 + ii] = sacc;

    // ---- partial accumulators straight to gmem (no normalize here) ----------
    float* pout = g_pacc[h];
#pragma unroll
    for (int mt = 0; mt < 4; ++mt) {
        const int row0 = mt * 16 + l4;
#pragma unroll
        for (int nt = 0; nt < 2; ++nt) {
            const int gcol = wf * 16 + nt * 8 + lm * 2;
            float2 v0, v1;
            v0.x = fragC[mt][nt][0];
            v0.y = fragC[mt][nt][1];
            v1.x = fragC[mt][nt][2];
            v1.y = fragC[mt][nt][3];
            *(float2*)&pout[(size_t)(i0 + row0) * FOUT + gcol]     = v0;
            *(float2*)&pout[(size_t)(i0 + row0 + 8) * FOUT + gcol] = v1;
        }
    }
#undef LOAD_ADJ
#undef STORE_P
}

// ---------------- Kernel D: combine halves, normalize, elu -------------------
__global__ void __launch_bounds__(256) combine_kernel(float* __restrict__ out) {
    const int idx = blockIdx.x * 256 + threadIdx.x;   // 262144 float4 slots
    const int row = idx >> 5;
    const int c4  = (idx & 31) << 2;
    const size_t off = (size_t)row * FOUT + c4;
    float4 a0 = *(const float4*)&g_pacc[0][off];
    float4 a1 = *(const float4*)&g_pacc[1][off];
    const float s = 1.f / (g_ps[0][row] + g_ps[1][row]);
    float4 o;
    o.x = (a0.x + a1.x) * s;
    o.y = (a0.y + a1.y) * s;
    o.z = (a0.z + a1.z) * s;
    o.w = (a0.w + a1.w) * s;
    o.x = (o.x > 0.f) ? o.x : expm1f(o.x);
    o.y = (o.y > 0.f) ? o.y : expm1f(o.y);
    o.z = (o.z > 0.f) ? o.z : expm1f(o.z);
    o.w = (o.w > 0.f) ? o.w : expm1f(o.w);
    *(float4*)&out[off] = o;
}

// ---------------- launch ------------------------------------------------------
extern "C" void kernel_launch(void* const* d_in, const int* in_sizes, int n_in,
                              void* d_out, int out_size) {
    const float* h   = (const float*)d_in[0];
    const int*   adj = (const int*)d_in[1];
    const float* W   = (const float*)d_in[2];
    const float* a   = (const float*)d_in[3];
    float*       out = (float*)d_out;

    wh_kernel<<<NN / 64, 256>>>(h, W, a);

    const int smem_bytes = (F2S_FLOATS + 2 * P_FLOATS) * sizeof(float); // 53248
    cudaFuncSetAttribute(gat_kernel, cudaFuncAttributeMaxDynamicSharedMemorySize, smem_bytes);
    gat_kernel<<<dim3(NN / 64, 2), 256, smem_bytes>>>(adj);

    combine_kernel<<<(NN * FOUT / 4) / 256, 256>>>(out);
}

// round 13
// speedup vs baseline: 1.7752x; 1.0593x over previous
#include <cuda_runtime.h>
#include <cstdint>
#include <cstddef>

#define NN   8192
#define FIN  256
#define FOUT 128
#define ALPHA_SLOPE 0.2f

#define PB_STRIDE 72
#define P_FLOATS  (64 * PB_STRIDE)     // 4608 per stage
#define NT_HALF   64                   // j-tiles per half
#define F2S_FLOATS 4096                // f2 slice per half

// ---------------- scratch (device globals: no allocation allowed) ------------
// g_WhB: Wh pre-staged in MMA-B fragment layout per 64-row j-tile:
//   addr = tile*8192 + kt*1024 + f*8 + (kl&3)*2 + (kl>>2),  row = tile*64+kt*8+kl
__device__ float g_WhB[(size_t)NN * FOUT];
__device__ float g_f1[NN];
__device__ float g_f2[NN];
// partial results per j-half
__device__ float g_pacc[2][(size_t)NN * FOUT];
__device__ float g_ps[2][NN];

// ---------------- helpers ----------------------------------------------------
__device__ __forceinline__ float to_tf32(float x) {
    uint32_t u;
    asm("cvt.rna.tf32.f32 %0, %1;" : "=r"(u) : "f"(x));
    return __uint_as_float(u);
}

__device__ __forceinline__ void mma_tf32(float* c,
                                         uint32_t a0, uint32_t a1, uint32_t a2, uint32_t a3,
                                         uint32_t b0, uint32_t b1) {
    asm volatile(
        "mma.sync.aligned.m16n8k8.row.col.f32.tf32.tf32.f32 "
        "{%0,%1,%2,%3}, {%4,%5,%6,%7}, {%8,%9}, {%0,%1,%2,%3};\n"
        : "+f"(c[0]), "+f"(c[1]), "+f"(c[2]), "+f"(c[3])
        : "r"(a0), "r"(a1), "r"(a2), "r"(a3), "r"(b0), "r"(b1));
}

__device__ __forceinline__ float lrelu_exp(float s) {
    s = fmaxf(s, ALPHA_SLOPE * s);
    return __expf(s);
}

__device__ __forceinline__ int4 ldcs4(const int4* p) {
    return __ldcs(p);   // streaming: adj is read exactly once
}

// ---------------- Kernel A: Wh = h@W (stored in B layout), f1, f2 ------------
__global__ void __launch_bounds__(256) wh_kernel(const float* __restrict__ h,
                                                 const float* __restrict__ W,
                                                 const float* __restrict__ a) {
    __shared__ float hs[64][64];
    __shared__ float Ws[64][FOUT];

    const int t  = threadIdx.x;
    const int i0 = blockIdx.x * 64;
    const int tf = t & 31;
    const int ti = t >> 5;

    float acc[8][4];
#pragma unroll
    for (int r = 0; r < 8; ++r)
#pragma unroll
        for (int c = 0; c < 4; ++c) acc[r][c] = 0.f;

    for (int kc = 0; kc < 4; ++kc) {
        __syncthreads();
#pragma unroll
        for (int idx = t; idx < 1024; idx += 256) {
            int row = idx >> 4, c = idx & 15;
            *(float4*)&hs[row][c * 4] =
                *(const float4*)&h[(size_t)(i0 + row) * FIN + kc * 64 + c * 4];
        }
#pragma unroll
        for (int idx = t; idx < 2048; idx += 256) {
            int row = idx >> 5, c = idx & 31;
            *(float4*)&Ws[row][c * 4] =
                *(const float4*)&W[(size_t)(kc * 64 + row) * FOUT + c * 4];
        }
        __syncthreads();
#pragma unroll 8
        for (int k = 0; k < 64; ++k) {
            float4 wv = *(float4*)&Ws[k][tf * 4];
#pragma unroll
            for (int r = 0; r < 8; ++r) {
                float hv = hs[ti * 8 + r][k];
                acc[r][0] += hv * wv.x;
                acc[r][1] += hv * wv.y;
                acc[r][2] += hv * wv.z;
                acc[r][3] += hv * wv.w;
            }
        }
    }

    float4 a1v = *(const float4*)&a[tf * 4];
    float4 a2v = *(const float4*)&a[FOUT + tf * 4];
#pragma unroll
    for (int r = 0; r < 8; ++r) {
        float v1 = acc[r][0] * a1v.x + acc[r][1] * a1v.y + acc[r][2] * a1v.z + acc[r][3] * a1v.w;
        float v2 = acc[r][0] * a2v.x + acc[r][1] * a2v.y + acc[r][2] * a2v.z + acc[r][3] * a2v.w;
#pragma unroll
        for (int off = 16; off > 0; off >>= 1) {
            v1 += __shfl_xor_sync(0xffffffffu, v1, off);
            v2 += __shfl_xor_sync(0xffffffffu, v2, off);
        }
        if (tf == 0) {
            g_f1[i0 + ti * 8 + r] = v1;
            g_f2[i0 + ti * 8 + r] = v2;
        }
    }

    float* base = &g_WhB[(size_t)blockIdx.x * 8192 + ti * 1024];
#pragma unroll
    for (int r = 0; r < 4; ++r) {
#pragma unroll
        for (int c = 0; c < 4; ++c) {
            float2 v;
            v.x = to_tf32(acc[r][c]);
            v.y = to_tf32(acc[r + 4][c]);
            *(float2*)&base[(tf * 4 + c) * 8 + r * 2] = v;
        }
    }
}

// ---------------- Kernel C: fused masked attention (partial over j-half) -----
// grid (128, 2), block 256 (8 warps), 2 blocks/SM. Block tile 64(i) x 128(f),
// j-tiles of 64 within half h. Warp tile 64(M) x 16(N), full K.
// 4-stage P ring, one __syncthreads per 2 tiles; B fragments loaded one tile
// ahead into reused registers (covered by STORE_P); adj prefetched 3 ahead.
__global__ void __launch_bounds__(256, 2) gat_kernel(const int* __restrict__ adj) {
    extern __shared__ float smem[];
    float* f2s = smem;                          // 4096 floats (this half)
    float* Pst = smem + F2S_FLOATS;             // 4 * P_FLOATS

    const int t    = threadIdx.x;
    const int lane = t & 31;
    const int wid  = t >> 5;
    const int i0   = blockIdx.x * 64;
    const int h    = blockIdx.y;

    const int ii  = t >> 2;           // P producer row (0..63)
    const int c16 = t & 3;            // P producer 16-col chunk

    const int wf = wid;               // 0..7 (N: 16 cols)
    const int l4 = lane >> 2;
    const int lm = lane & 3;

    const float f1i = g_f1[i0 + ii];
    float sacc = 0.f;

    float fragC[4][2][4];
#pragma unroll
    for (int mt = 0; mt < 4; ++mt)
#pragma unroll
        for (int nt = 0; nt < 2; ++nt)
#pragma unroll
            for (int c = 0; c < 4; ++c) fragC[mt][nt][c] = 0.f;

    // stage this half's f2 into smem
    for (int idx = t; idx < F2S_FLOATS / 4; idx += 256)
        *(float4*)&f2s[idx * 4] =
            *(const float4*)&g_f2[h * F2S_FLOATS + idx * 4];

    // invariant addresses
    const int4* adj_base = (const int4*)(adj + (size_t)(i0 + ii) * NN
                                         + h * F2S_FLOATS + c16 * 16);
    const float* bwarp = g_WhB + (wf * 16 + l4) * 8 + lm * 2;
    float* ppd = &Pst[ii * PB_STRIDE + c16 * 16];   // + stage*P_FLOATS

    int4 adjA, adjB, adjC, adjD;
    float2 bb[8][2];

#define LOAD_ADJ(JT)                                                        \
    do {                                                                    \
        const int4* ap = adj_base + (size_t)(JT) * 16;                      \
        adjA = ldcs4(ap);                                                   \
        adjB = ldcs4(ap + 1);                                               \
        adjC = ldcs4(ap + 2);                                               \
        adjD = ldcs4(ap + 3);                                               \
    } while (0)

#define BB_LOAD(JT)                                                        \
    do {                                                                   \
        const float* bt = bwarp + (size_t)(h * NT_HALF + (JT)) * 8192;     \
        _Pragma("unroll")                                                  \
        for (int k2 = 0; k2 < 8; ++k2) {                                   \
            bb[k2][0] = *(const float2*)(bt + k2 * 1024);                  \
            bb[k2][1] = *(const float2*)(bt + k2 * 1024 + 64);             \
        }                                                                  \
    } while (0)

// P written permuted per 8-col group: col q -> slot (q&3)*2 + (q>>2)
// slots = [c0,c4,c1,c5,c2,c6,c3,c7]; A-frag (col lm, lm+4) is one float2.
#define STORE_P(ST, JT)                                                     \
    do {                                                                    \
        float* pd = ppd + (ST) * P_FLOATS;                                  \
        const float* f2p = f2s + (JT) * 64 + c16 * 16;                      \
        _Pragma("unroll")                                                   \
        for (int e = 0; e < 2; ++e) {                                       \
            const int4 ma = e ? adjC : adjA;                                \
            const int4 mbv = e ? adjD : adjB;                               \
            float4 fa = *(const float4*)(f2p + e * 8);                      \
            float4 fb = *(const float4*)(f2p + e * 8 + 4);                  \
            float4 pva, pvb;                                                \
            pva.x = (ma.x > 0)  ? to_tf32(lrelu_exp(f1i + fa.x)) : 0.f;     \
            pva.y = (ma.y > 0)  ? to_tf32(lrelu_exp(f1i + fa.y)) : 0.f;     \
            pva.z = (ma.z > 0)  ? to_tf32(lrelu_exp(f1i + fa.z)) : 0.f;     \
            pva.w = (ma.w > 0)  ? to_tf32(lrelu_exp(f1i + fa.w)) : 0.f;     \
            pvb.x = (mbv.x > 0) ? to_tf32(lrelu_exp(f1i + fb.x)) : 0.f;     \
            pvb.y = (mbv.y > 0) ? to_tf32(lrelu_exp(f1i + fb.y)) : 0.f;     \
            pvb.z = (mbv.z > 0) ? to_tf32(lrelu_exp(f1i + fb.z)) : 0.f;     \
            pvb.w = (mbv.w > 0) ? to_tf32(lrelu_exp(f1i + fb.w)) : 0.f;     \
            float4 q0 = make_float4(pva.x, pvb.x, pva.y, pvb.y);            \
            float4 q1 = make_float4(pva.z, pvb.z, pva.w, pvb.w);            \
            *(float4*)(pd + e * 8)     = q0;                                \
            *(float4*)(pd + e * 8 + 4) = q1;                                \
            sacc += pva.x + pva.y + pva.z + pva.w                           \
                  + pvb.x + pvb.y + pvb.z + pvb.w;                          \
        }                                                                   \
    } while (0)

    // ---- prologue: P(0), P(1) into stages 0,1; B(0) in regs -----------------
    LOAD_ADJ(0);
    __syncthreads();        // f2s staged
    STORE_P(0, 0);
    LOAD_ADJ(1);
    STORE_P(1, 1);
    LOAD_ADJ(2);
    BB_LOAD(0);
    __syncthreads();        // stages 0,1 visible

#pragma unroll 2
    for (int jt = 0; jt < NT_HALF; ++jt) {
        // ---- MMA on stage jt&3 with preloaded bb ---------------------------
        const float* Pc    = Pst + (jt & 3) * P_FLOATS;
        const float* abase = Pc + l4 * PB_STRIDE + lm * 2;
#pragma unroll
        for (int k2 = 0; k2 < 8; ++k2) {
            uint32_t a0[4], a1[4], a2[4], a3[4];
#pragma unroll
            for (int mt = 0; mt < 4; ++mt) {
                const float* pAm = abase + mt * 16 * PB_STRIDE + k2 * 8;
                float2 lo = *(const float2*)pAm;
                float2 hi = *(const float2*)(pAm + 8 * PB_STRIDE);
                a0[mt] = __float_as_uint(lo.x);
                a2[mt] = __float_as_uint(lo.y);
                a1[mt] = __float_as_uint(hi.x);
                a3[mt] = __float_as_uint(hi.y);
            }
#pragma unroll
            for (int nt = 0; nt < 2; ++nt) {
                uint32_t b0 = __float_as_uint(bb[k2][nt].x);
                uint32_t b1 = __float_as_uint(bb[k2][nt].y);
#pragma unroll
                for (int mt = 0; mt < 4; ++mt)
                    mma_tf32(fragC[mt][nt], a0[mt], a1[mt], a2[mt], a3[mt], b0, b1);
            }
        }

        // ---- B for next tile into the now-dead bb regs (covered by STORE_P)
        if (jt + 1 < NT_HALF) BB_LOAD(jt + 1);

        // ---- build P two tiles ahead; adj three ahead ----------------------
        if (jt + 2 < NT_HALF) {
            STORE_P((jt + 2) & 3, jt + 2);
            if (jt + 3 < NT_HALF) LOAD_ADJ(jt + 3);
        }

        if (jt & 1) __syncthreads();   // one barrier per 2 tiles
    }

    // ---- partial row sums: reduce across the 4 producers of each row --------
    sacc += __shfl_xor_sync(0xffffffffu, sacc, 1);
    sacc += __shfl_xor_sync(0xffffffffu, sacc, 2);
    if (c16 == 0) g_ps[h][i0 + ii] = sacc;

    // ---- partial accumulators straight to gmem (no normalize here) ----------
    float* pout = g_pacc[h];
#pragma unroll
    for (int mt = 0; mt < 4; ++mt) {
        const int row0 = mt * 16 + l4;
#pragma unroll
        for (int nt = 0; nt < 2; ++nt) {
            const int gcol = wf * 16 + nt * 8 + lm * 2;
            float2 v0, v1;
            v0.x = fragC[mt][nt][0];
            v0.y = fragC[mt][nt][1];
            v1.x = fragC[mt][nt][2];
            v1.y = fragC[mt][nt][3];
            *(float2*)&pout[(size_t)(i0 + row0) * FOUT + gcol]     = v0;
            *(float2*)&pout[(size_t)(i0 + row0 + 8) * FOUT + gcol] = v1;
        }
    }
#undef LOAD_ADJ
#undef BB_LOAD
#undef STORE_P
}

// ---------------- Kernel D: combine halves, normalize, elu -------------------
__global__ void __launch_bounds__(256) combine_kernel(float* __restrict__ out) {
    const int idx = blockIdx.x * 256 + threadIdx.x;   // 262144 float4 slots
    const int row = idx >> 5;
    const int c4  = (idx & 31) << 2;
    const size_t off = (size_t)row * FOUT + c4;
    float4 a0 = *(const float4*)&g_pacc[0][off];
    float4 a1 = *(const float4*)&g_pacc[1][off];
    const float s = 1.f / (g_ps[0][row] + g_ps[1][row]);
    float4 o;
    o.x = (a0.x + a1.x) * s;
    o.y = (a0.y + a1.y) * s;
    o.z = (a0.z + a1.z) * s;
    o.w = (a0.w + a1.w) * s;
    o.x = (o.x > 0.f) ? o.x : expm1f(o.x);
    o.y = (o.y > 0.f) ? o.y : expm1f(o.y);
    o.z = (o.z > 0.f) ? o.z : expm1f(o.z);
    o.w = (o.w > 0.f) ? o.w : expm1f(o.w);
    *(float4*)&out[off] = o;
}

// ---------------- launch ------------------------------------------------------
extern "C" void kernel_launch(void* const* d_in, const int* in_sizes, int n_in,
                              void* d_out, int out_size) {
    const float* h   = (const float*)d_in[0];
    const int*   adj = (const int*)d_in[1];
    const float* W   = (const float*)d_in[2];
    const float* a   = (const float*)d_in[3];
    float*       out = (float*)d_out;

    wh_kernel<<<NN / 64, 256>>>(h, W, a);

    const int smem_bytes = (F2S_FLOATS + 4 * P_FLOATS) * sizeof(float); // 90112
    cudaFuncSetAttribute(gat_kernel, cudaFuncAttributeMaxDynamicSharedMemorySize, smem_bytes);
    gat_kernel<<<dim3(NN / 64, 2), 256, smem_bytes>>>(adj);

    combine_kernel<<<(NN * FOUT / 4) / 256, 256>>>(out);
}

// round 14
// speedup vs baseline: 2.1584x; 1.2159x over previous
#include <cuda_runtime.h>
#include <cstdint>
#include <cstddef>

#define NN   8192
#define FIN  256
#define FOUT 128
#define ALPHA_SLOPE 0.2f

#define P4_STAGE  1152                 // float4 per P stage (4*288)
#define NT_HALF   64                   // j-tiles per half
#define F2S_FLOATS 4096                // f2 slice per half

// ---------------- scratch (device globals: no allocation allowed) ------------
// g_WhB: Wh in B-fragment float4 layout per 64-row j-tile (2048 float4/tile):
//   float4 idx = tile*2048 + kt*256 + fq*32 + l4*4 + lm
//     = { v[f=fq*16+l4, kl=lm], v[f, kl=lm+4], v[f+8, kl=lm], v[f+8, kl=lm+4] }
__device__ float g_WhB[(size_t)NN * FOUT];
__device__ float g_f1[NN];
__device__ float g_f2[NN];
// partial results per j-half
__device__ float g_pacc[2][(size_t)NN * FOUT];
__device__ float g_ps[2][NN];

// ---------------- helpers ----------------------------------------------------
__device__ __forceinline__ float to_tf32(float x) {
    uint32_t u;
    asm("cvt.rna.tf32.f32 %0, %1;" : "=r"(u) : "f"(x));
    return __uint_as_float(u);
}

__device__ __forceinline__ void mma_tf32(float* c,
                                         uint32_t a0, uint32_t a1, uint32_t a2, uint32_t a3,
                                         uint32_t b0, uint32_t b1) {
    asm volatile(
        "mma.sync.aligned.m16n8k8.row.col.f32.tf32.tf32.f32 "
        "{%0,%1,%2,%3}, {%4,%5,%6,%7}, {%8,%9}, {%0,%1,%2,%3};\n"
        : "+f"(c[0]), "+f"(c[1]), "+f"(c[2]), "+f"(c[3])
        : "r"(a0), "r"(a1), "r"(a2), "r"(a3), "r"(b0), "r"(b1));
}

__device__ __forceinline__ float lrelu_exp(float s) {
    s = fmaxf(s, ALPHA_SLOPE * s);
    return __expf(s);
}

__device__ __forceinline__ int4 ldcs4(const int4* p) {
    return __ldcs(p);   // streaming: adj is read exactly once
}

// ---------------- Kernel A: Wh = h@W (B-frag layout), f1, f2 -----------------
__global__ void __launch_bounds__(256) wh_kernel(const float* __restrict__ h,
                                                 const float* __restrict__ W,
                                                 const float* __restrict__ a) {
    __shared__ float hs[64][64];
    __shared__ float Ws[64][FOUT];

    const int t  = threadIdx.x;
    const int i0 = blockIdx.x * 64;
    const int tf = t & 31;
    const int ti = t >> 5;          // kt

    float acc[8][4];
#pragma unroll
    for (int r = 0; r < 8; ++r)
#pragma unroll
        for (int c = 0; c < 4; ++c) acc[r][c] = 0.f;

    for (int kc = 0; kc < 4; ++kc) {
        __syncthreads();
#pragma unroll
        for (int idx = t; idx < 1024; idx += 256) {
            int row = idx >> 4, c = idx & 15;
            *(float4*)&hs[row][c * 4] =
                *(const float4*)&h[(size_t)(i0 + row) * FIN + kc * 64 + c * 4];
        }
#pragma unroll
        for (int idx = t; idx < 2048; idx += 256) {
            int row = idx >> 5, c = idx & 31;
            *(float4*)&Ws[row][c * 4] =
                *(const float4*)&W[(size_t)(kc * 64 + row) * FOUT + c * 4];
        }
        __syncthreads();
#pragma unroll 8
        for (int k = 0; k < 64; ++k) {
            float4 wv = *(float4*)&Ws[k][tf * 4];
#pragma unroll
            for (int r = 0; r < 8; ++r) {
                float hv = hs[ti * 8 + r][k];
                acc[r][0] += hv * wv.x;
                acc[r][1] += hv * wv.y;
                acc[r][2] += hv * wv.z;
                acc[r][3] += hv * wv.w;
            }
        }
    }

    float4 a1v = *(const float4*)&a[tf * 4];
    float4 a2v = *(const float4*)&a[FOUT + tf * 4];
#pragma unroll
    for (int r = 0; r < 8; ++r) {
        float v1 = acc[r][0] * a1v.x + acc[r][1] * a1v.y + acc[r][2] * a1v.z + acc[r][3] * a1v.w;
        float v2 = acc[r][0] * a2v.x + acc[r][1] * a2v.y + acc[r][2] * a2v.z + acc[r][3] * a2v.w;
#pragma unroll
        for (int off = 16; off > 0; off >>= 1) {
            v1 += __shfl_xor_sync(0xffffffffu, v1, off);
            v2 += __shfl_xor_sync(0xffffffffu, v2, off);
        }
        if (tf == 0) {
            g_f1[i0 + ti * 8 + r] = v1;
            g_f2[i0 + ti * 8 + r] = v2;
        }
    }

    // store into B-frag float4 layout (see g_WhB comment); pairs {kl=lm, lm+4}
    float* base = &g_WhB[(size_t)blockIdx.x * 8192 + ti * 1024];
#pragma unroll
    for (int c = 0; c < 4; ++c) {
        const int f   = tf * 4 + c;
        const int fq  = f >> 4;
        const int p8  = (f >> 3) & 1;
        const int l4f = f & 7;
        float* dst = base + fq * 128 + l4f * 16 + p8 * 2;
#pragma unroll
        for (int lm = 0; lm < 4; ++lm) {
            float2 v;
            v.x = to_tf32(acc[lm][c]);
            v.y = to_tf32(acc[lm + 4][c]);
            *(float2*)(dst + lm * 4) = v;
        }
    }
}

// ---------------- Kernel C: fused masked attention (partial over j-half) -----
// grid (128, 2), block 256 (8 warps), 2 blocks/SM. Block tile 64(i) x 128(f).
// Warp tile 32(M) x 32(N): wi = wid>>2, wf = wid&3. Full K per tile.
// P in smem as float4 A-fragments with c8-rotation (conflict-free STS/LDS.128):
//   float4 at a*288 + l4*36 + c8*4 + ((lm+c8)&3)
//     = { P[r][c8*8+lm], P[r+8][...], P[r][c8*8+lm+4], P[r+8][...] }, r=a*16+l4.
// B via coalesced LDG.128 from g_WhB; k2 0-3 preloaded, k2 4-7 at MMA start.
__global__ void __launch_bounds__(256, 2) gat_kernel(const int* __restrict__ adj) {
    extern __shared__ float smem[];
    float* f2s = smem;                          // 4096 floats (this half)
    float4* Pst4 = (float4*)(smem + F2S_FLOATS); // 4 stages x 1152 float4

    const int t    = threadIdx.x;
    const int lane = t & 31;
    const int wid  = t >> 5;
    const int i0   = blockIdx.x * 64;
    const int h    = blockIdx.y;

    // producer mapping: row-pair + 8-col chunk
    const int ii2 = t >> 3;           // 0..31
    const int c8  = t & 7;            // k2 group
    const int pa  = ii2 >> 3;         // atom 0..3
    const int l4i = ii2 & 7;
    const int r0  = pa * 16 + l4i;
    const int r1  = r0 + 8;

    // consumer mapping
    const int wi = wid >> 2;          // 0..1 (M)
    const int wf = wid & 3;           // 0..3 (N)
    const int l4 = lane >> 2;
    const int lm = lane & 3;

    const float f1r0 = g_f1[i0 + r0];
    const float f1r1 = g_f1[i0 + r1];
    float sacc0 = 0.f, sacc1 = 0.f;

    float fragC[2][4][4];
#pragma unroll
    for (int mt = 0; mt < 2; ++mt)
#pragma unroll
        for (int nt = 0; nt < 4; ++nt)
#pragma unroll
            for (int c = 0; c < 4; ++c) fragC[mt][nt][c] = 0.f;

    // stage this half's f2 into smem
    for (int idx = t; idx < F2S_FLOATS / 4; idx += 256)
        *(float4*)&f2s[idx * 4] =
            *(const float4*)&g_f2[h * F2S_FLOATS + idx * 4];

    // invariant addresses
    const int4* aptr0 = (const int4*)(adj + (size_t)(i0 + r0) * NN
                                      + h * F2S_FLOATS + c8 * 8);
    const int4* aptr1 = (const int4*)(adj + (size_t)(i0 + r1) * NN
                                      + h * F2S_FLOATS + c8 * 8);
    float4* pw4 = Pst4 + pa * 288 + l4i * 36 + c8 * 4;       // + stage*1152 + slot
    const float4* abase4 = Pst4 + wi * 576 + l4 * 36;        // + stage*1152
    const float4* bw4 = (const float4*)g_WhB + wf * 64 + l4 * 4 + lm;

    int4 adj0a, adj0b, adj1a, adj1b;
    float4 bba[4][2], bbb[4][2];

#define LOAD_ADJ(JT)                                                        \
    do {                                                                    \
        adj0a = ldcs4(aptr0 + (size_t)(JT) * 16);                           \
        adj0b = ldcs4(aptr0 + (size_t)(JT) * 16 + 1);                       \
        adj1a = ldcs4(aptr1 + (size_t)(JT) * 16);                           \
        adj1b = ldcs4(aptr1 + (size_t)(JT) * 16 + 1);                       \
    } while (0)

#define BBA_LOAD(JT)                                                        \
    do {                                                                    \
        const float4* bt = bw4 + (size_t)(h * NT_HALF + (JT)) * 2048;       \
        _Pragma("unroll")                                                   \
        for (int k2 = 0; k2 < 4; ++k2) {                                    \
            bba[k2][0] = bt[k2 * 256];                                      \
            bba[k2][1] = bt[k2 * 256 + 32];                                 \
        }                                                                   \
    } while (0)

#define BBB_LOAD(JT)                                                        \
    do {                                                                    \
        const float4* bt = bw4 + (size_t)(h * NT_HALF + (JT)) * 2048 + 1024;\
        _Pragma("unroll")                                                   \
        for (int k2 = 0; k2 < 4; ++k2) {                                    \
            bbb[k2][0] = bt[k2 * 256];                                      \
            bbb[k2][1] = bt[k2 * 256 + 32];                                 \
        }                                                                   \
    } while (0)

#define STORE_P(ST, JT)                                                     \
    do {                                                                    \
        float4* pd = pw4 + (ST) * P4_STAGE;                                 \
        const float* f2p = f2s + (JT) * 64 + c8 * 8;                        \
        float4 fa = *(const float4*)(f2p);                                  \
        float4 fb = *(const float4*)(f2p + 4);                              \
        float p00, p01, p02, p03, p04, p05, p06, p07;                       \
        float p10, p11, p12, p13, p14, p15, p16, p17;                       \
        p00 = (adj0a.x > 0) ? to_tf32(lrelu_exp(f1r0 + fa.x)) : 0.f;        \
        p01 = (adj0a.y > 0) ? to_tf32(lrelu_exp(f1r0 + fa.y)) : 0.f;        \
        p02 = (adj0a.z > 0) ? to_tf32(lrelu_exp(f1r0 + fa.z)) : 0.f;        \
        p03 = (adj0a.w > 0) ? to_tf32(lrelu_exp(f1r0 + fa.w)) : 0.f;        \
        p04 = (adj0b.x > 0) ? to_tf32(lrelu_exp(f1r0 + fb.x)) : 0.f;        \
        p05 = (adj0b.y > 0) ? to_tf32(lrelu_exp(f1r0 + fb.y)) : 0.f;        \
        p06 = (adj0b.z > 0) ? to_tf32(lrelu_exp(f1r0 + fb.z)) : 0.f;        \
        p07 = (adj0b.w > 0) ? to_tf32(lrelu_exp(f1r0 + fb.w)) : 0.f;        \
        p10 = (adj1a.x > 0) ? to_tf32(lrelu_exp(f1r1 + fa.x)) : 0.f;        \
        p11 = (adj1a.y > 0) ? to_tf32(lrelu_exp(f1r1 + fa.y)) : 0.f;        \
        p12 = (adj1a.z > 0) ? to_tf32(lrelu_exp(f1r1 + fa.z)) : 0.f;        \
        p13 = (adj1a.w > 0) ? to_tf32(lrelu_exp(f1r1 + fa.w)) : 0.f;        \
        p14 = (adj1b.x > 0) ? to_tf32(lrelu_exp(f1r1 + fb.x)) : 0.f;        \
        p15 = (adj1b.y > 0) ? to_tf32(lrelu_exp(f1r1 + fb.y)) : 0.f;        \
        p16 = (adj1b.z > 0) ? to_tf32(lrelu_exp(f1r1 + fb.z)) : 0.f;        \
        p17 = (adj1b.w > 0) ? to_tf32(lrelu_exp(f1r1 + fb.w)) : 0.f;        \
        pd[(0 + c8) & 3] = make_float4(p00, p10, p04, p14);                 \
        pd[(1 + c8) & 3] = make_float4(p01, p11, p05, p15);                 \
        pd[(2 + c8) & 3] = make_float4(p02, p12, p06, p16);                 \
        pd[(3 + c8) & 3] = make_float4(p03, p13, p07, p17);                 \
        sacc0 += p00 + p01 + p02 + p03 + p04 + p05 + p06 + p07;             \
        sacc1 += p10 + p11 + p12 + p13 + p14 + p15 + p16 + p17;             \
    } while (0)

#define MMA_K2(K2, QB)                                                      \
    do {                                                                    \
        float4 qa0 = pA[(K2) * 4 + ((lm + (K2)) & 3)];                      \
        float4 qa1 = pA[288 + (K2) * 4 + ((lm + (K2)) & 3)];                \
        _Pragma("unroll")                                                   \
        for (int p2 = 0; p2 < 2; ++p2) {                                    \
            uint32_t b0 = __float_as_uint((QB)[p2].x);                      \
            uint32_t b1 = __float_as_uint((QB)[p2].y);                      \
            uint32_t b2 = __float_as_uint((QB)[p2].z);                      \
            uint32_t b3 = __float_as_uint((QB)[p2].w);                      \
            mma_tf32(fragC[0][2 * p2], __float_as_uint(qa0.x),              \
                     __float_as_uint(qa0.y), __float_as_uint(qa0.z),        \
                     __float_as_uint(qa0.w), b0, b1);                       \
            mma_tf32(fragC[0][2 * p2 + 1], __float_as_uint(qa0.x),          \
                     __float_as_uint(qa0.y), __float_as_uint(qa0.z),        \
                     __float_as_uint(qa0.w), b2, b3);                       \
            mma_tf32(fragC[1][2 * p2], __float_as_uint(qa1.x),              \
                     __float_as_uint(qa1.y), __float_as_uint(qa1.z),        \
                     __float_as_uint(qa1.w), b0, b1);                       \
            mma_tf32(fragC[1][2 * p2 + 1], __float_as_uint(qa1.x),          \
                     __float_as_uint(qa1.y), __float_as_uint(qa1.z),        \
                     __float_as_uint(qa1.w), b2, b3);                       \
        }                                                                   \
    } while (0)

    // ---- prologue: P(0), P(1) into stages 0,1; B(0) k2 0-3 in regs ----------
    LOAD_ADJ(0);
    __syncthreads();        // f2s staged
    STORE_P(0, 0);
    LOAD_ADJ(1);
    STORE_P(1, 1);
    LOAD_ADJ(2);
    BBA_LOAD(0);
    __syncthreads();        // stages 0,1 visible

#pragma unroll 2
    for (int jt = 0; jt < NT_HALF; ++jt) {
        // ---- B k2 4-7 for this tile (covered by first 4 k2 of MMA) ---------
        BBB_LOAD(jt);

        // ---- MMA on stage jt&3 ---------------------------------------------
        const float4* pA = abase4 + (jt & 3) * P4_STAGE;
        MMA_K2(0, bba[0]); MMA_K2(1, bba[1]);
        MMA_K2(2, bba[2]); MMA_K2(3, bba[3]);
        MMA_K2(4, bbb[0]); MMA_K2(5, bbb[1]);
        MMA_K2(6, bbb[2]); MMA_K2(7, bbb[3]);

        // ---- B k2 0-3 for next tile (covered by STORE_P + barrier) ---------
        if (jt + 1 < NT_HALF) BBA_LOAD(jt + 1);

        // ---- build P two tiles ahead; adj three ahead ----------------------
        if (jt + 2 < NT_HALF) {
            STORE_P((jt + 2) & 3, jt + 2);
            if (jt + 3 < NT_HALF) LOAD_ADJ(jt + 3);
        }

        if (jt & 1) __syncthreads();   // one barrier per 2 tiles
    }

    // ---- partial row sums: reduce across the 8 producers of each row-pair ---
    sacc0 += __shfl_xor_sync(0xffffffffu, sacc0, 1);
    sacc0 += __shfl_xor_sync(0xffffffffu, sacc0, 2);
    sacc0 += __shfl_xor_sync(0xffffffffu, sacc0, 4);
    sacc1 += __shfl_xor_sync(0xffffffffu, sacc1, 1);
    sacc1 += __shfl_xor_sync(0xffffffffu, sacc1, 2);
    sacc1 += __shfl_xor_sync(0xffffffffu, sacc1, 4);
    if (c8 == 0) {
        g_ps[h][i0 + r0] = sacc0;
        g_ps[h][i0 + r1] = sacc1;
    }

    // ---- partial accumulators straight to gmem ------------------------------
    float* pout = g_pacc[h];
#pragma unroll
    for (int mt = 0; mt < 2; ++mt) {
        const int row0 = wi * 32 + mt * 16 + l4;
#pragma unroll
        for (int nt = 0; nt < 4; ++nt) {
            const int gcol = wf * 32 + nt * 8 + lm * 2;
            float2 v0, v1;
            v0.x = fragC[mt][nt][0];
            v0.y = fragC[mt][nt][1];
            v1.x = fragC[mt][nt][2];
            v1.y = fragC[mt][nt][3];
            *(float2*)&pout[(size_t)(i0 + row0) * FOUT + gcol]     = v0;
            *(float2*)&pout[(size_t)(i0 + row0 + 8) * FOUT + gcol] = v1;
        }
    }
#undef LOAD_ADJ
#undef BBA_LOAD
#undef BBB_LOAD
#undef STORE_P
#undef MMA_K2
}

// ---------------- Kernel D: combine halves, normalize, elu -------------------
__global__ void __launch_bounds__(256) combine_kernel(float* __restrict__ out) {
    const int idx = blockIdx.x * 256 + threadIdx.x;
    const int row = idx >> 5;
    const int c4  = (idx & 31) << 2;
    const size_t off = (size_t)row * FOUT + c4;
    float4 a0 = *(const float4*)&g_pacc[0][off];
    float4 a1 = *(const float4*)&g_pacc[1][off];
    const float s = 1.f / (g_ps[0][row] + g_ps[1][row]);
    float4 o;
    o.x = (a0.x + a1.x) * s;
    o.y = (a0.y + a1.y) * s;
    o.z = (a0.z + a1.z) * s;
    o.w = (a0.w + a1.w) * s;
    o.x = (o.x > 0.f) ? o.x : expm1f(o.x);
    o.y = (o.y > 0.f) ? o.y : expm1f(o.y);
    o.z = (o.z > 0.f) ? o.z : expm1f(o.z);
    o.w = (o.w > 0.f) ? o.w : expm1f(o.w);
    *(float4*)&out[off] = o;
}

// ---------------- launch ------------------------------------------------------
extern "C" void kernel_launch(void* const* d_in, const int* in_sizes, int n_in,
                              void* d_out, int out_size) {
    const float* h   = (const float*)d_in[0];
    const int*   adj = (const int*)d_in[1];
    const float* W   = (const float*)d_in[2];
    const float* a   = (const float*)d_in[3];
    float*       out = (float*)d_out;

    wh_kernel<<<NN / 64, 256>>>(h, W, a);

    const int smem_bytes = F2S_FLOATS * 4 + 4 * P4_STAGE * 16;   // 90112 B
    cudaFuncSetAttribute(gat_kernel, cudaFuncAttributeMaxDynamicSharedMemorySize, smem_bytes);
    gat_kernel<<<dim3(NN / 64, 2), 256, smem_bytes>>>(adj);

    combine_kernel<<<(NN * FOUT / 4) / 256, 256>>>(out);
}

// round 15
// speedup vs baseline: 2.5227x; 1.1688x over previous
#include <cuda_runtime.h>
#include <cuda_fp16.h>
#include <cstdint>
#include <cstddef>

#define NN   8192
#define FIN  256
#define FOUT 128
#define ALPHA_SLOPE 0.2f

#define P4_STAGE  576                  // uint4 per P stage (16 groups x 36)
#define NT_HALF   64                   // j-tiles per half
#define F2S_FLOATS 4096                // f2 slice per half

// ---------------- scratch (device globals: no allocation allowed) ------------
// g_WhB2: Wh in fp16 MMA-B fragment layout per 64-row j-tile (1024 uint4/tile):
//   uint4 idx = tile*1024 + ks*256 + g*32 + l4*4 + lm   (g = f>>4)
//   halves = { Wh[2lm][f], Wh[2lm+1][f], Wh[2lm+8][f], Wh[2lm+9][f],
//              same 4 for f+8 },  f = g*16 + l4, j rel to tile*64 + ks*16.
__device__ __half2 g_WhB2[(size_t)NN * FOUT / 2];
__device__ float g_f1[NN];
__device__ float g_f2[NN];
__device__ float g_f2max_val;
// partial results per j-half
__device__ float g_pacc[2][(size_t)NN * FOUT];
__device__ float g_ps[2][NN];

// ---------------- helpers ----------------------------------------------------
__device__ __forceinline__ void mma_f16(float* c,
                                        uint32_t a0, uint32_t a1, uint32_t a2, uint32_t a3,
                                        uint32_t b0, uint32_t b1) {
    asm volatile(
        "mma.sync.aligned.m16n8k16.row.col.f32.f16.f16.f32 "
        "{%0,%1,%2,%3}, {%4,%5,%6,%7}, {%8,%9}, {%0,%1,%2,%3};\n"
        : "+f"(c[0]), "+f"(c[1]), "+f"(c[2]), "+f"(c[3])
        : "r"(a0), "r"(a1), "r"(a2), "r"(a3), "r"(b0), "r"(b1));
}

__device__ __forceinline__ int4 ldcs4(const int4* p) {
    return __ldcs(p);   // streaming: adj is read exactly once
}

__device__ __forceinline__ uint32_t packh2(float lo, float hi) {
    __half2 h = __floats2half2_rn(lo, hi);
    return *(uint32_t*)&h;
}

// ---------------- Kernel A: Wh = h@W (fp16 B-frag layout), f1, f2 ------------
// grid 256 (32 rows/block), block 256, 2 blocks/SM.
__global__ void __launch_bounds__(256, 2) wh_kernel(const float* __restrict__ h,
                                                    const float* __restrict__ W,
                                                    const float* __restrict__ a) {
    __shared__ float hs[32][64];
    __shared__ float Ws[64][FOUT];

    const int t  = threadIdx.x;
    const int i0 = blockIdx.x * 32;
    const int tf = t & 31;          // 4 output cols tf*4..+3
    const int ti = t >> 5;          // 4 output rows ti*4..+3

    float acc[4][4];
#pragma unroll
    for (int r = 0; r < 4; ++r)
#pragma unroll
        for (int c = 0; c < 4; ++c) acc[r][c] = 0.f;

    for (int kc = 0; kc < 4; ++kc) {
        __syncthreads();
#pragma unroll
        for (int idx = t; idx < 512; idx += 256) {       // h tile 32x64
            int row = idx >> 4, c = idx & 15;
            *(float4*)&hs[row][c * 4] =
                *(const float4*)&h[(size_t)(i0 + row) * FIN + kc * 64 + c * 4];
        }
#pragma unroll
        for (int idx = t; idx < 2048; idx += 256) {      // W tile 64x128
            int row = idx >> 5, c = idx & 31;
            *(float4*)&Ws[row][c * 4] =
                *(const float4*)&W[(size_t)(kc * 64 + row) * FOUT + c * 4];
        }
        __syncthreads();
#pragma unroll 8
        for (int k = 0; k < 64; ++k) {
            float4 wv = *(float4*)&Ws[k][tf * 4];
#pragma unroll
            for (int r = 0; r < 4; ++r) {
                float hv = hs[ti * 4 + r][k];
                acc[r][0] += hv * wv.x;
                acc[r][1] += hv * wv.y;
                acc[r][2] += hv * wv.z;
                acc[r][3] += hv * wv.w;
            }
        }
    }

    float4 a1v = *(const float4*)&a[tf * 4];
    float4 a2v = *(const float4*)&a[FOUT + tf * 4];
#pragma unroll
    for (int r = 0; r < 4; ++r) {
        float v1 = acc[r][0] * a1v.x + acc[r][1] * a1v.y + acc[r][2] * a1v.z + acc[r][3] * a1v.w;
        float v2 = acc[r][0] * a2v.x + acc[r][1] * a2v.y + acc[r][2] * a2v.z + acc[r][3] * a2v.w;
#pragma unroll
        for (int off = 16; off > 0; off >>= 1) {
            v1 += __shfl_xor_sync(0xffffffffu, v1, off);
            v2 += __shfl_xor_sync(0xffffffffu, v2, off);
        }
        if (tf == 0) {
            g_f1[i0 + ti * 4 + r] = v1;
            g_f2[i0 + ti * 4 + r] = v2;
        }
    }

    // store fp16 into B-fragment layout (see g_WhB2 comment)
#pragma unroll
    for (int q = 0; q < 2; ++q) {
        const int j    = i0 + ti * 4 + 2 * q;      // even row, pairs (j, j+1)
        const int tile = j >> 6;
        const int ks   = (j >> 4) & 3;
        const int lmj  = (j & 7) >> 1;
        const int j8   = (j >> 3) & 1;
#pragma unroll
        for (int c = 0; c < 4; ++c) {
            const int f  = tf * 4 + c;
            const int gg = f >> 4;
            const int fl = f & 7;
            const int f8 = (f >> 3) & 1;
            __half2 v = __floats2half2_rn(acc[2 * q][c], acc[2 * q + 1][c]);
            g_WhB2[(size_t)(tile * 1024 + ks * 256 + gg * 32 + fl * 4 + lmj) * 4
                   + j8 + f8 * 2] = v;
        }
    }
}

// ---------------- Kernel B: F2MAX = max_j f2[j] ------------------------------
__global__ void __launch_bounds__(1024) f2max_kernel() {
    __shared__ float red[32];
    const int t = threadIdx.x;
    float m = -1e30f;
    for (int i = t; i < NN; i += 1024) m = fmaxf(m, g_f2[i]);
#pragma unroll
    for (int off = 16; off > 0; off >>= 1)
        m = fmaxf(m, __shfl_xor_sync(0xffffffffu, m, off));
    if ((t & 31) == 0) red[t >> 5] = m;
    __syncthreads();
    if (t < 32) {
        m = red[t];
#pragma unroll
        for (int off = 16; off > 0; off >>= 1)
            m = fmaxf(m, __shfl_xor_sync(0xffffffffu, m, off));
        if (t == 0) g_f2max_val = m;
    }
}

// ---------------- Kernel C: fused masked attention (fp16 MMA, j-half) --------
// grid (128, 2), block 256 (8 warps), 2 blocks/SM. Block tile 64(i) x 128(f).
// Warp tile 32(M) x 32(N), m16n8k16 fp16, full K per tile.
// P' = exp(lrelu(f1+f2) - m_i) in (0,1] (m_i = lrelu(f1_i + F2MAX)) -> fp16 safe.
// P smem layout: uint4 idx = (pa*4+ks)*36 + l4*4 + slot, slot = (p + (ks>>1))&3,
//   uint4 = A-frag {a0,a1,a2,a3} for rows (pa*16+l4, +8), cols pair p of k-step.
__global__ void __launch_bounds__(256, 2) gat_kernel(const int* __restrict__ adj) {
    extern __shared__ float smem[];
    float* f2s = smem;                              // 4096 floats (this half)
    uint4* Pst4 = (uint4*)(smem + F2S_FLOATS);      // 4 stages x 576 uint4

    const int t    = threadIdx.x;
    const int lane = t & 31;
    const int wid  = t >> 5;
    const int i0   = blockIdx.x * 64;
    const int h    = blockIdx.y;

    // producer mapping
    const int ii2   = t >> 3;         // 0..31 row-pairs
    const int c8    = t & 7;
    const int pa    = ii2 >> 3;       // 16-row atom
    const int l4i   = ii2 & 7;
    const int r0    = pa * 16 + l4i;
    const int r1    = r0 + 8;
    const int ksp   = c8 >> 1;        // k-step owned
    const int lmsel = c8 & 1;
    const int rkp   = ksp >> 1;
    const int sl0   = (2 * lmsel + rkp) & 3;
    const int sl1   = (2 * lmsel + 1 + rkp) & 3;

    // consumer mapping
    const int wi = wid >> 2;          // 0..1 (M)
    const int wf = wid & 3;           // 0..3 (N)
    const int l4 = lane >> 2;
    const int lm = lane & 3;

    const float f1r0 = g_f1[i0 + r0];
    const float f1r1 = g_f1[i0 + r1];
    const float F2M  = g_f2max_val;
    float s0 = f1r0 + F2M;
    float s1 = f1r1 + F2M;
    const float m0 = fmaxf(s0, ALPHA_SLOPE * s0);
    const float m1 = fmaxf(s1, ALPHA_SLOPE * s1);
    float sacc0 = 0.f, sacc1 = 0.f;

    float fragC[2][4][4];
#pragma unroll
    for (int mt = 0; mt < 2; ++mt)
#pragma unroll
        for (int nt = 0; nt < 4; ++nt)
#pragma unroll
            for (int c = 0; c < 4; ++c) fragC[mt][nt][c] = 0.f;

    // stage this half's f2 into smem
    for (int idx = t; idx < F2S_FLOATS / 4; idx += 256)
        *(float4*)&f2s[idx * 4] =
            *(const float4*)&g_f2[h * F2S_FLOATS + idx * 4];

    // invariant addresses
    const int4* ap0 = (const int4*)(adj + (size_t)(i0 + r0) * NN + h * F2S_FLOATS)
                      + ksp * 4 + lmsel;
    const int4* ap1 = (const int4*)(adj + (size_t)(i0 + r1) * NN + h * F2S_FLOATS)
                      + ksp * 4 + lmsel;
    uint4* pw = Pst4 + (pa * 4 + ksp) * 36 + l4i * 4;
    const float* f2base = f2s + ksp * 16 + 4 * lmsel;           // + jt*64
    const uint4* bw = (const uint4*)g_WhB2 + wf * 64 + l4 * 4 + lm;
    const uint4* abase = Pst4 + (wi * 8) * 36 + l4 * 4;

    int4 adj0a, adj0b, adj1a, adj1b;
    uint4 bba[4], bbb[4];     // bba: (ks0,u0),(ks0,u1),(ks1,u0),(ks1,u1); bbb: ks2,ks3

#define LOAD_ADJ(JT)                                                        \
    do {                                                                    \
        adj0a = ldcs4(ap0 + (size_t)(JT) * 16);                             \
        adj0b = ldcs4(ap0 + (size_t)(JT) * 16 + 2);                         \
        adj1a = ldcs4(ap1 + (size_t)(JT) * 16);                             \
        adj1b = ldcs4(ap1 + (size_t)(JT) * 16 + 2);                         \
    } while (0)

#define BBA_LOAD(JT)                                                        \
    do {                                                                    \
        const uint4* bt = bw + (size_t)(h * NT_HALF + (JT)) * 1024;         \
        bba[0] = bt[0];   bba[1] = bt[32];                                  \
        bba[2] = bt[256]; bba[3] = bt[288];                                 \
    } while (0)

#define BBB_LOAD(JT)                                                        \
    do {                                                                    \
        const uint4* bt = bw + (size_t)(h * NT_HALF + (JT)) * 1024;         \
        bbb[0] = bt[512]; bbb[1] = bt[544];                                 \
        bbb[2] = bt[768]; bbb[3] = bt[800];                                 \
    } while (0)

#define EG(AV, F1, MM, FX) \
    (((AV) > 0) ? __expf(fmaxf((F1) + (FX), ALPHA_SLOPE * ((F1) + (FX))) - (MM)) : 0.f)

#define STORE_P(ST, JT)                                                     \
    do {                                                                    \
        uint4* pd = pw + (ST) * P4_STAGE;                                   \
        const float* fp = f2base + (JT) * 64;                               \
        float4 fa = *(const float4*)fp;                                     \
        float4 fb = *(const float4*)(fp + 8);                               \
        float e0a = EG(adj0a.x, f1r0, m0, fa.x);                            \
        float e0b = EG(adj0a.y, f1r0, m0, fa.y);                            \
        float e0c = EG(adj0a.z, f1r0, m0, fa.z);                            \
        float e0d = EG(adj0a.w, f1r0, m0, fa.w);                            \
        float e0e = EG(adj0b.x, f1r0, m0, fb.x);                            \
        float e0f = EG(adj0b.y, f1r0, m0, fb.y);                            \
        float e0g = EG(adj0b.z, f1r0, m0, fb.z);                            \
        float e0h = EG(adj0b.w, f1r0, m0, fb.w);                            \
        float e1a = EG(adj1a.x, f1r1, m1, fa.x);                            \
        float e1b = EG(adj1a.y, f1r1, m1, fa.y);                            \
        float e1c = EG(adj1a.z, f1r1, m1, fa.z);                            \
        float e1d = EG(adj1a.w, f1r1, m1, fa.w);                            \
        float e1e = EG(adj1b.x, f1r1, m1, fb.x);                            \
        float e1f = EG(adj1b.y, f1r1, m1, fb.y);                            \
        float e1g = EG(adj1b.z, f1r1, m1, fb.z);                            \
        float e1h = EG(adj1b.w, f1r1, m1, fb.w);                            \
        uint4 q0, q1;                                                       \
        q0.x = packh2(e0a, e0b); q0.y = packh2(e1a, e1b);                   \
        q0.z = packh2(e0e, e0f); q0.w = packh2(e1e, e1f);                   \
        q1.x = packh2(e0c, e0d); q1.y = packh2(e1c, e1d);                   \
        q1.z = packh2(e0g, e0h); q1.w = packh2(e1g, e1h);                   \
        pd[sl0] = q0;                                                       \
        pd[sl1] = q1;                                                       \
        sacc0 += e0a + e0b + e0c + e0d + e0e + e0f + e0g + e0h;             \
        sacc1 += e1a + e1b + e1c + e1d + e1e + e1f + e1g + e1h;             \
    } while (0)

#define MMA_KS(KS, BB0, BB1)                                                \
    do {                                                                    \
        const int slot = (lm + ((KS) >> 1)) & 3;                            \
        uint4 qa0 = pA[(KS) * 36 + slot];                                   \
        uint4 qa1 = pA[(4 + (KS)) * 36 + slot];                             \
        mma_f16(fragC[0][0], qa0.x, qa0.y, qa0.z, qa0.w, (BB0).x, (BB0).y); \
        mma_f16(fragC[0][1], qa0.x, qa0.y, qa0.z, qa0.w, (BB0).z, (BB0).w); \
        mma_f16(fragC[0][2], qa0.x, qa0.y, qa0.z, qa0.w, (BB1).x, (BB1).y); \
        mma_f16(fragC[0][3], qa0.x, qa0.y, qa0.z, qa0.w, (BB1).z, (BB1).w); \
        mma_f16(fragC[1][0], qa1.x, qa1.y, qa1.z, qa1.w, (BB0).x, (BB0).y); \
        mma_f16(fragC[1][1], qa1.x, qa1.y, qa1.z, qa1.w, (BB0).z, (BB0).w); \
        mma_f16(fragC[1][2], qa1.x, qa1.y, qa1.z, qa1.w, (BB1).x, (BB1).y); \
        mma_f16(fragC[1][3], qa1.x, qa1.y, qa1.z, qa1.w, (BB1).z, (BB1).w); \
    } while (0)

    // ---- prologue: P(0), P(1) into stages 0,1; B(0) ks0-1 in regs ----------
    LOAD_ADJ(0);
    __syncthreads();        // f2s staged
    STORE_P(0, 0);
    LOAD_ADJ(1);
    STORE_P(1, 1);
    LOAD_ADJ(2);
    BBA_LOAD(0);
    __syncthreads();        // stages 0,1 visible

#pragma unroll 2
    for (int jt = 0; jt < NT_HALF; ++jt) {
        // B ks2-3 for this tile (covered by first half of MMA)
        BBB_LOAD(jt);

        const uint4* pA = abase + (jt & 3) * P4_STAGE;
        MMA_KS(0, bba[0], bba[1]);
        MMA_KS(1, bba[2], bba[3]);
        MMA_KS(2, bbb[0], bbb[1]);
        MMA_KS(3, bbb[2], bbb[3]);

        // B ks0-1 for next tile (covered by STORE_P + barrier)
        if (jt + 1 < NT_HALF) BBA_LOAD(jt + 1);

        // build P two tiles ahead; adj three ahead
        if (jt + 2 < NT_HALF) {
            STORE_P((jt + 2) & 3, jt + 2);
            if (jt + 3 < NT_HALF) LOAD_ADJ(jt + 3);
        }

        if (jt & 1) __syncthreads();   // one barrier per 2 tiles
    }

    // ---- partial row sums: reduce across the 8 producers of each row-pair ---
    sacc0 += __shfl_xor_sync(0xffffffffu, sacc0, 1);
    sacc0 += __shfl_xor_sync(0xffffffffu, sacc0, 2);
    sacc0 += __shfl_xor_sync(0xffffffffu, sacc0, 4);
    sacc1 += __shfl_xor_sync(0xffffffffu, sacc1, 1);
    sacc1 += __shfl_xor_sync(0xffffffffu, sacc1, 2);
    sacc1 += __shfl_xor_sync(0xffffffffu, sacc1, 4);
    if (c8 == 0) {
        g_ps[h][i0 + r0] = sacc0;
        g_ps[h][i0 + r1] = sacc1;
    }

    // ---- partial accumulators straight to gmem ------------------------------
    float* pout = g_pacc[h];
#pragma unroll
    for (int mt = 0; mt < 2; ++mt) {
        const int row0 = wi * 32 + mt * 16 + l4;
#pragma unroll
        for (int nt = 0; nt < 4; ++nt) {
            const int gcol = wf * 32 + nt * 8 + lm * 2;
            float2 v0, v1;
            v0.x = fragC[mt][nt][0];
            v0.y = fragC[mt][nt][1];
            v1.x = fragC[mt][nt][2];
            v1.y = fragC[mt][nt][3];
            *(float2*)&pout[(size_t)(i0 + row0) * FOUT + gcol]     = v0;
            *(float2*)&pout[(size_t)(i0 + row0 + 8) * FOUT + gcol] = v1;
        }
    }
#undef LOAD_ADJ
#undef BBA_LOAD
#undef BBB_LOAD
#undef EG
#undef STORE_P
#undef MMA_KS
}

// ---------------- Kernel D: combine halves, normalize, elu -------------------
__global__ void __launch_bounds__(256) combine_kernel(float* __restrict__ out) {
    const int idx = blockIdx.x * 256 + threadIdx.x;
    const int row = idx >> 5;
    const int c4  = (idx & 31) << 2;
    const size_t off = (size_t)row * FOUT + c4;
    float4 a0 = *(const float4*)&g_pacc[0][off];
    float4 a1 = *(const float4*)&g_pacc[1][off];
    const float s = 1.f / (g_ps[0][row] + g_ps[1][row]);
    float4 o;
    o.x = (a0.x + a1.x) * s;
    o.y = (a0.y + a1.y) * s;
    o.z = (a0.z + a1.z) * s;
    o.w = (a0.w + a1.w) * s;
    o.x = (o.x > 0.f) ? o.x : expm1f(o.x);
    o.y = (o.y > 0.f) ? o.y : expm1f(o.y);
    o.z = (o.z > 0.f) ? o.z : expm1f(o.z);
    o.w = (o.w > 0.f) ? o.w : expm1f(o.w);
    *(float4*)&out[off] = o;
}

// ---------------- launch ------------------------------------------------------
extern "C" void kernel_launch(void* const* d_in, const int* in_sizes, int n_in,
                              void* d_out, int out_size) {
    const float* h   = (const float*)d_in[0];
    const int*   adj = (const int*)d_in[1];
    const float* W   = (const float*)d_in[2];
    const float* a   = (const float*)d_in[3];
    float*       out = (float*)d_out;

    wh_kernel<<<NN / 32, 256>>>(h, W, a);
    f2max_kernel<<<1, 1024>>>();

    const int smem_bytes = F2S_FLOATS * 4 + 4 * P4_STAGE * 16;   // 53248 B
    cudaFuncSetAttribute(gat_kernel, cudaFuncAttributeMaxDynamicSharedMemorySize, smem_bytes);
    gat_kernel<<<dim3(NN / 64, 2), 256, smem_bytes>>>(adj);

    combine_kernel<<<(NN * FOUT / 4) / 256, 256>>>(out);
}